// round 1
// baseline (speedup 1.0000x reference)
#include <cuda_runtime.h>
#include <math.h>

#define BATCH 8
#define LSEQ  4096
#define DIN   256
#define DOUTC 256
#define M_TOT (BATCH*LSEQ)   // 32768
#define N_TOT 1536           // 2 dirs * 3 gates * 256
#define K_TOT 768            // 3 taps * 256

// Scratch (static device globals; no allocation in kernel_launch)
__device__ float g_wt[K_TOT * N_TOT];                    // [kk][c]  (~4.7 MB)
__device__ float g_gates[(size_t)M_TOT * N_TOT];         // activated gates (~201 MB)

// ---------------------------------------------------------------------------
// Kernel 1: rearrange weights W[c, i, tap] -> g_wt[kk = tap*256+i][c]
// ---------------------------------------------------------------------------
__global__ void prep_weights(const float* __restrict__ Wf,
                             const float* __restrict__ Wb) {
    int idx = blockIdx.x * blockDim.x + threadIdx.x;
    if (idx >= K_TOT * N_TOT) return;
    int kk = idx / N_TOT;
    int c  = idx - kk * N_TOT;
    int tap = kk >> 8;
    int i   = kk & 255;
    float v = (c < 768) ? Wf[c * 768 + i * 3 + tap]
                        : Wb[(c - 768) * 768 + i * 3 + tap];
    g_wt[idx] = v;
}

// ---------------------------------------------------------------------------
// Kernel 2: fused im2col SGEMM + bias + activation
// gates[m, c] = act( sum_kk A[m,kk] * g_wt[kk,c] + bias[c] )
// A[m, kk=tap*256+i] = x[b, l+tap-1, i]  (0 at sequence edges)
// BM=128, BN=128, BK=16, 256 threads, 8x8 per thread
// ---------------------------------------------------------------------------
__global__ __launch_bounds__(256, 2)
void gemm_gates(const float* __restrict__ x,
                const float* __restrict__ bf,
                const float* __restrict__ bb) {
    __shared__ float As[16][128];
    __shared__ float Bs[16][128];

    const int n0  = blockIdx.x * 128;
    const int m0  = blockIdx.y * 128;
    const int tid = threadIdx.x;
    const int tx  = tid & 15;
    const int ty  = tid >> 4;

    // A-load mapping: thread -> (row, 4-float column group)
    const int a_r = tid >> 2;         // 0..63
    const int a_c = (tid & 3) * 4;    // 0,4,8,12
    // B-load mapping
    const int b_r = tid >> 4;         // 0..15
    const int b_c = (tid & 15) * 4;   // 0..60

    float acc[8][8];
#pragma unroll
    for (int p = 0; p < 8; p++)
#pragma unroll
        for (int q = 0; q < 8; q++) acc[p][q] = 0.f;

    for (int kk0 = 0; kk0 < K_TOT; kk0 += 16) {
        const int tap = kk0 >> 8;        // constant across the 16-slice
        const int i0  = kk0 & 255;

        // Load A tile (im2col on the fly)
#pragma unroll
        for (int h = 0; h < 2; h++) {
            int r  = a_r + h * 64;
            int m  = m0 + r;
            int l  = m & (LSEQ - 1);
            int sl = l + tap - 1;
            float4 v = make_float4(0.f, 0.f, 0.f, 0.f);
            if (sl >= 0 && sl < LSEQ)
                v = *(const float4*)(x + (size_t)(m + tap - 1) * DIN + i0 + a_c);
            As[a_c + 0][r] = v.x;
            As[a_c + 1][r] = v.y;
            As[a_c + 2][r] = v.z;
            As[a_c + 3][r] = v.w;
        }
        // Load B tile (coalesced from pre-transposed weights)
#pragma unroll
        for (int h = 0; h < 2; h++) {
            int c = b_c + h * 64;
            float4 v = *(const float4*)(g_wt + (size_t)(kk0 + b_r) * N_TOT + n0 + c);
            *(float4*)&Bs[b_r][c] = v;
        }
        __syncthreads();

#pragma unroll
        for (int k = 0; k < 16; k++) {
            float a[8], b[8];
            *(float4*)&a[0] = *(const float4*)&As[k][ty * 8];
            *(float4*)&a[4] = *(const float4*)&As[k][ty * 8 + 4];
            *(float4*)&b[0] = *(const float4*)&Bs[k][tx * 8];
            *(float4*)&b[4] = *(const float4*)&Bs[k][tx * 8 + 4];
#pragma unroll
            for (int p = 0; p < 8; p++)
#pragma unroll
                for (int q = 0; q < 8; q++)
                    acc[p][q] += a[p] * b[q];
        }
        __syncthreads();
    }

    // Epilogue: bias + activation. A 128-wide N-block never crosses a 256-wide
    // gate chunk, so gate type is uniform per block.
    const int chunk = n0 >> 8;          // 0..5
    const int ctype = chunk % 3;        // 0,1 -> sigmoid; 2 -> tanh

    float bias[8];
#pragma unroll
    for (int q = 0; q < 8; q++) {
        int c = n0 + tx * 8 + q;
        bias[q] = (c < 768) ? bf[c] : bb[c - 768];
    }

#pragma unroll
    for (int p = 0; p < 8; p++) {
        int m = m0 + ty * 8 + p;
        float out[8];
#pragma unroll
        for (int q = 0; q < 8; q++) {
            float v = acc[p][q] + bias[q];
            if (ctype == 2) {
                // stable tanh
                float t = __expf(-2.f * fabsf(v));
                float r = (1.f - t) / (1.f + t);
                out[q] = copysignf(r, v);
            } else {
                out[q] = 1.f / (1.f + __expf(-v));
            }
        }
        float* dst = g_gates + (size_t)m * N_TOT + n0 + tx * 8;
        *(float4*)dst       = *(float4*)&out[0];
        *(float4*)(dst + 4) = *(float4*)&out[4];
    }
}

// ---------------------------------------------------------------------------
// Kernel 3: bidirectional fo-pool scan + output assembly
// 16 blocks: (dir, batch); 256 threads = channel d.
// out layout: [B,L,512] output, then [B,512] last_h, then [B,512] last_c
// ---------------------------------------------------------------------------
__global__ void scan_kernel(float* __restrict__ out) {
    const int bx  = blockIdx.x;
    const int dir = bx >> 3;
    const int b   = bx & 7;
    const int d   = threadIdx.x;

    const size_t OUT_HL = (size_t)BATCH * LSEQ * 512;

    float c = 0.f;
    float h = 0.f;

    if (dir == 0) {
        const float* gp = g_gates + (size_t)b * LSEQ * N_TOT + d;
        float*       op = out + (size_t)b * LSEQ * 512 + d;
#pragma unroll 4
        for (int l = 0; l < LSEQ; l++) {
            float f = gp[0];
            float o = gp[256];
            float z = gp[512];
            c = f * c + (1.f - f) * z;
            h = c * o;
            *op = h;
            gp += N_TOT;
            op += 512;
        }
        out[OUT_HL + b * 512 + d]        = h;   // hidden[:, L-1]
        out[OUT_HL + 4096 + b * 512 + d] = c;   // cell[:, L-1]
    } else {
        const float* gp = g_gates + ((size_t)b * LSEQ + (LSEQ - 1)) * N_TOT + 768 + d;
        float*       op = out + ((size_t)b * LSEQ + (LSEQ - 1)) * 512 + 256 + d;
        float h_last = 0.f, c_last = 0.f;
#pragma unroll 4
        for (int l = LSEQ - 1; l >= 0; l--) {
            float f = gp[0];
            float o = gp[256];
            float z = gp[512];
            c = f * c + (1.f - f) * z;
            h = c * o;
            *op = h;
            if (l == LSEQ - 1) { h_last = h; c_last = c; }  // first step = rhidden[:, -1]
            gp -= N_TOT;
            op -= 512;
        }
        out[OUT_HL + b * 512 + 256 + d]        = h_last;
        out[OUT_HL + 4096 + b * 512 + 256 + d] = c_last;
    }
}

// ---------------------------------------------------------------------------
extern "C" void kernel_launch(void* const* d_in, const int* in_sizes, int n_in,
                              void* d_out, int out_size) {
    const float* x  = (const float*)d_in[0];   // [8,4096,256]
    // d_in[1] = lengths (unused by reference)
    const float* Wf = (const float*)d_in[2];   // [768,256,3]
    const float* bf = (const float*)d_in[3];   // [768]
    const float* Wb = (const float*)d_in[4];   // [768,256,3]
    const float* bb = (const float*)d_in[5];   // [768]
    float* out = (float*)d_out;

    // 1) weight relayout
    {
        int total = K_TOT * N_TOT;
        prep_weights<<<(total + 255) / 256, 256>>>(Wf, Wb);
    }
    // 2) fused conv-GEMM + activation
    {
        dim3 grid(N_TOT / 128, M_TOT / 128);   // (12, 256)
        gemm_gates<<<grid, 256>>>(x, bf, bb);
    }
    // 3) bidirectional scan + output
    scan_kernel<<<16, 256>>>(out);
}

// round 3
// speedup vs baseline: 2.6192x; 2.6192x over previous
#include <cuda_runtime.h>
#include <cuda_bf16.h>
#include <stdint.h>
#include <math.h>

#define BATCH 8
#define LSEQ  4096
#define DIN   256
#define M_TOT 32768
#define N_TOT 1536
#define K_TOT 768
#define LP    4098   // padded rows per batch (one zero row each side)

// ---------------- scratch (static device globals) ----------------
__device__ __align__(16) __nv_bfloat16 g_xhi[BATCH * LP * DIN];
__device__ __align__(16) __nv_bfloat16 g_xlo[BATCH * LP * DIN];
__device__ __align__(16) __nv_bfloat16 g_whi[N_TOT * K_TOT];
__device__ __align__(16) __nv_bfloat16 g_wlo[N_TOT * K_TOT];
__device__ float g_gates[(size_t)M_TOT * N_TOT];
// chunked-scan scratch: [dir][b][chunk][d]
#define NCH 64
#define CHLEN 64
__device__ float g_F[2 * BATCH * NCH * 256];
__device__ float g_Cz[2 * BATCH * NCH * 256];
__device__ float g_init[2 * BATCH * NCH * 256];

// ---------------- PTX helpers (arch-agnostic, compute_80-era) ----------------
__device__ __forceinline__ uint32_t smem_u32(const void* p) {
    uint32_t a;
    asm("{ .reg .u64 t; cvta.to.shared.u64 t, %1; cvt.u32.u64 %0, t; }" : "=r"(a) : "l"(p));
    return a;
}
__device__ __forceinline__ void cp16(uint32_t dst, const void* src) {
    asm volatile("cp.async.cg.shared.global [%0], [%1], 16;" :: "r"(dst), "l"(src));
}
__device__ __forceinline__ void cp_commit() {
    asm volatile("cp.async.commit_group;" ::: "memory");
}
template<int N> __device__ __forceinline__ void cp_wait() {
    asm volatile("cp.async.wait_group %0;" :: "n"(N) : "memory");
}
__device__ __forceinline__ void ldsm4(uint32_t* r, uint32_t addr) {
    asm volatile("ldmatrix.sync.aligned.m8n8.x4.shared.b16 {%0,%1,%2,%3}, [%4];"
                 : "=r"(r[0]), "=r"(r[1]), "=r"(r[2]), "=r"(r[3]) : "r"(addr));
}
__device__ __forceinline__ void mma_bf16(float* d, const uint32_t* a, uint32_t b0, uint32_t b1) {
    asm volatile("mma.sync.aligned.m16n8k16.row.col.f32.bf16.bf16.f32 "
                 "{%0,%1,%2,%3}, {%4,%5,%6,%7}, {%8,%9}, {%0,%1,%2,%3};"
                 : "+f"(d[0]), "+f"(d[1]), "+f"(d[2]), "+f"(d[3])
                 : "r"(a[0]), "r"(a[1]), "r"(a[2]), "r"(a[3]), "r"(b0), "r"(b1));
}

// ---------------------------------------------------------------------------
// Kernel 1: convert + pad x -> bf16 hi/lo  (rows: b*(L+2) + (l+1))
// ---------------------------------------------------------------------------
__global__ void prep_x(const float* __restrict__ x) {
    int idx = blockIdx.x * blockDim.x + threadIdx.x;
    const int TOT8 = BATCH * LP * DIN / 8;
    if (idx >= TOT8) return;
    int e0 = idx * 8;
    int b = e0 / (LP * DIN);
    int rem = e0 - b * LP * DIN;
    int r = rem / DIN;
    int i = rem - r * DIN;
    int l = r - 1;
    float v[8];
    if (l >= 0 && l < LSEQ) {
        const float4* src = (const float4*)(x + ((size_t)(b * LSEQ + l)) * DIN + i);
        float4 a = src[0], c = src[1];
        v[0]=a.x; v[1]=a.y; v[2]=a.z; v[3]=a.w; v[4]=c.x; v[5]=c.y; v[6]=c.z; v[7]=c.w;
    } else {
#pragma unroll
        for (int j = 0; j < 8; j++) v[j] = 0.f;
    }
    __nv_bfloat16 hi[8], lo[8];
#pragma unroll
    for (int j = 0; j < 8; j++) {
        hi[j] = __float2bfloat16(v[j]);
        lo[j] = __float2bfloat16(v[j] - __bfloat162float(hi[j]));
    }
    *(uint4*)(g_xhi + e0) = *(uint4*)hi;
    *(uint4*)(g_xlo + e0) = *(uint4*)lo;
}

// ---------------------------------------------------------------------------
// Kernel 2: weights -> [c][kk=tap*256+i] bf16 hi/lo
// ---------------------------------------------------------------------------
__global__ void prep_w(const float* __restrict__ Wf, const float* __restrict__ Wb) {
    int idx = blockIdx.x * blockDim.x + threadIdx.x;
    if (idx >= N_TOT * K_TOT) return;
    int c = idx / K_TOT;
    int kk = idx - c * K_TOT;
    int tap = kk >> 8;
    int i = kk & 255;
    float v = (c < 768) ? Wf[c * 768 + i * 3 + tap] : Wb[(c - 768) * 768 + i * 3 + tap];
    __nv_bfloat16 hi = __float2bfloat16(v);
    g_whi[idx] = hi;
    g_wlo[idx] = __float2bfloat16(v - __bfloat162float(hi));
}

// ---------------------------------------------------------------------------
// Kernel 3: bf16-split HMMA GEMM + bias + activation -> g_gates
// BM=256, BN=128, BK=32, 256 threads, warp tile 64x64, 4-stage cp.async
// Iteration space: 3 terms x 24 K-chunks = 72
// ---------------------------------------------------------------------------
#define STAGES 4
#define STAGE_BYTES 24576     // A: 256*64B = 16384, B: 128*64B = 8192
#define GEMM_SMEM (STAGES * STAGE_BYTES)
#define NIT 72

__device__ __forceinline__ float actv(float v, int ctype) {
    if (ctype == 2) {
        float t = __expf(-2.f * fabsf(v));
        float r = (1.f - t) / (1.f + t);
        return copysignf(r, v);
    }
    return 1.f / (1.f + __expf(-v));
}

__device__ __forceinline__ void gemm_issue(uint32_t smemU, int stage, int j,
                                           int rbase, int n0, int tid) {
    int t = j / 24;
    int kchunk = j - t * 24;
    int kc = kchunk * 32;
    int tap = kc >> 8;
    int i0 = kc & 255;
    const __nv_bfloat16* Asrc = (t < 2) ? g_xhi : g_xlo;
    const __nv_bfloat16* Bsrc = (t == 1) ? g_wlo : g_whi;
    uint32_t abase = smemU + stage * STAGE_BYTES;
    uint32_t bbase = abase + 16384;
#pragma unroll
    for (int q = 0; q < 4; q++) {
        int idx = tid + q * 256;
        int row = idx >> 2, c16 = idx & 3;
        int chunk = c16 ^ (row & 3) ^ ((row >> 2) & 1);
        cp16(abase + row * 64 + chunk * 16,
             Asrc + (size_t)(rbase + tap + row) * 256 + i0 + c16 * 8);
    }
#pragma unroll
    for (int q = 0; q < 2; q++) {
        int idx = tid + q * 256;
        int row = idx >> 2, c16 = idx & 3;
        int chunk = c16 ^ (row & 3) ^ ((row >> 2) & 1);
        cp16(bbase + row * 64 + chunk * 16,
             Bsrc + (size_t)(n0 + row) * 768 + kc + c16 * 8);
    }
}

__global__ __launch_bounds__(256, 1)
void gemm_hmma(const float* __restrict__ bfv, const float* __restrict__ bbv) {
    extern __shared__ char smem[];
    uint32_t smemU = smem_u32(smem);
    const int tid = threadIdx.x;
    const int lane = tid & 31;
    const int w = tid >> 5;
    const int wm = w >> 1;          // 0..3
    const int wn = w & 1;           // 0..1
    const int n0 = blockIdx.x * 128;
    const int m0 = blockIdx.y * 256;
    const int batch = m0 >> 12;
    const int l0 = m0 & 4095;
    const int rbase = batch * LP + l0;

    // per-thread ldmatrix read offsets (within a stage)
    const int lr = lane & 7;
    const int grp = lane >> 3;
    const int arow = wm * 64 + (grp & 1) * 8 + lr;
    const int achk = (grp >> 1) ^ (arow & 3) ^ ((arow >> 2) & 1);
    const uint32_t aoff0 = (uint32_t)(arow * 64 + achk * 16);
    const int brow = wn * 64 + (grp >> 1) * 8 + lr;
    const int bchk = (grp & 1) ^ (brow & 3) ^ ((brow >> 2) & 1);
    const uint32_t boff0 = (uint32_t)(16384 + brow * 64 + bchk * 16);

    float acc[4][8][4];
#pragma unroll
    for (int mt = 0; mt < 4; mt++)
#pragma unroll
        for (int nt = 0; nt < 8; nt++)
#pragma unroll
            for (int r = 0; r < 4; r++) acc[mt][nt][r] = 0.f;

    // prologue: fill 3 stages
#pragma unroll
    for (int s = 0; s < STAGES - 1; s++) {
        gemm_issue(smemU, s, s, rbase, n0, tid);
        cp_commit();
    }

#pragma unroll 1
    for (int j = 0; j < NIT; j++) {
        cp_wait<STAGES - 2>();
        __syncthreads();
        if (j + STAGES - 1 < NIT)
            gemm_issue(smemU, (j + STAGES - 1) & (STAGES - 1), j + STAGES - 1, rbase, n0, tid);
        cp_commit();

        uint32_t stbase = smemU + (j & (STAGES - 1)) * STAGE_BYTES;
#pragma unroll
        for (int ks = 0; ks < 2; ks++) {
            uint32_t a[4][4], b[4][4];
#pragma unroll
            for (int mt = 0; mt < 4; mt++)
                ldsm4(a[mt], (stbase + aoff0 + mt * 1024) ^ (ks * 32));
#pragma unroll
            for (int np = 0; np < 4; np++)
                ldsm4(b[np], (stbase + boff0 + np * 1024) ^ (ks * 32));
#pragma unroll
            for (int mt = 0; mt < 4; mt++)
#pragma unroll
                for (int nt = 0; nt < 8; nt++)
                    mma_bf16(acc[mt][nt], a[mt], b[nt >> 1][(nt & 1) * 2], b[nt >> 1][(nt & 1) * 2 + 1]);
        }
    }

    // epilogue: bias + activation
    const int ctype = (n0 >> 8) % 3;
    const float* bsrc = (n0 < 768) ? bfv : bbv;
    const int cofs = (n0 < 768) ? n0 : (n0 - 768);

#pragma unroll
    for (int mt = 0; mt < 4; mt++) {
        int mrow = m0 + wm * 64 + mt * 16 + (lane >> 2);
        float* d0 = g_gates + (size_t)mrow * N_TOT + n0;
        float* d1 = d0 + (size_t)8 * N_TOT;
#pragma unroll
        for (int nt = 0; nt < 8; nt++) {
            int cc = wn * 64 + nt * 8 + (lane & 3) * 2;
            float bb0 = bsrc[cofs + cc];
            float bb1 = bsrc[cofs + cc + 1];
            float2 v0, v1;
            v0.x = actv(acc[mt][nt][0] + bb0, ctype);
            v0.y = actv(acc[mt][nt][1] + bb1, ctype);
            v1.x = actv(acc[mt][nt][2] + bb0, ctype);
            v1.y = actv(acc[mt][nt][3] + bb1, ctype);
            *(float2*)(d0 + cc) = v0;
            *(float2*)(d1 + cc) = v1;
        }
    }
}

// ---------------------------------------------------------------------------
// Chunked bidirectional fo-pool scan
// c_t = f c_{t-1} + (1-f) z   composed per chunk as c_end = F*c0 + Cz
// ---------------------------------------------------------------------------
__global__ void scanA() {
    int bid = blockIdx.x;
    int dir = bid >> 9;
    int rem = bid & 511;
    int b = rem >> 6;
    int ch = rem & 63;
    int d = threadIdx.x;

    float F = 1.f, c = 0.f;
    if (dir == 0) {
        const float* gp = g_gates + (size_t)(b * LSEQ + ch * CHLEN) * N_TOT + d;
#pragma unroll 4
        for (int s = 0; s < CHLEN; s++) {
            float f = gp[0], z = gp[512];
            c = f * c + (1.f - f) * z;
            F *= f;
            gp += N_TOT;
        }
    } else {
        const float* gp = g_gates + (size_t)(b * LSEQ + ch * CHLEN + CHLEN - 1) * N_TOT + 768 + d;
#pragma unroll 4
        for (int s = 0; s < CHLEN; s++) {
            float f = gp[0], z = gp[512];
            c = f * c + (1.f - f) * z;
            F *= f;
            gp -= N_TOT;
        }
    }
    int idx = ((dir * BATCH + b) * NCH + ch) * 256 + d;
    g_F[idx] = F;
    g_Cz[idx] = c;
}

__global__ void scanB() {
    int dir = blockIdx.x >> 3;
    int b = blockIdx.x & 7;
    int d = threadIdx.x;
    float c = 0.f;
    if (dir == 0) {
        for (int ch = 0; ch < NCH; ch++) {
            int idx = ((b) * NCH + ch) * 256 + d;
            g_init[idx] = c;
            c = g_F[idx] * c + g_Cz[idx];
        }
    } else {
        for (int ch = NCH - 1; ch >= 0; ch--) {
            int idx = ((BATCH + b) * NCH + ch) * 256 + d;
            g_init[idx] = c;
            c = g_F[idx] * c + g_Cz[idx];
        }
    }
}

__global__ void scanC(float* __restrict__ out) {
    int bid = blockIdx.x;
    int dir = bid >> 9;
    int rem = bid & 511;
    int b = rem >> 6;
    int ch = rem & 63;
    int d = threadIdx.x;
    const size_t OUT_HL = (size_t)BATCH * LSEQ * 512;

    float c = g_init[((dir * BATCH + b) * NCH + ch) * 256 + d];
    if (dir == 0) {
        const float* gp = g_gates + (size_t)(b * LSEQ + ch * CHLEN) * N_TOT + d;
        float* op = out + (size_t)(b * LSEQ + ch * CHLEN) * 512 + d;
        float h = 0.f;
#pragma unroll 4
        for (int s = 0; s < CHLEN; s++) {
            float f = gp[0], o = gp[256], z = gp[512];
            c = f * c + (1.f - f) * z;
            h = c * o;
            *op = h;
            gp += N_TOT;
            op += 512;
        }
        if (ch == NCH - 1) {
            out[OUT_HL + b * 512 + d]        = h;
            out[OUT_HL + 4096 + b * 512 + d] = c;
        }
    } else {
        const float* gp = g_gates + (size_t)(b * LSEQ + ch * CHLEN + CHLEN - 1) * N_TOT + 768 + d;
        float* op = out + (size_t)(b * LSEQ + ch * CHLEN + CHLEN - 1) * 512 + 256 + d;
        float h_first = 0.f, c_first = 0.f;
#pragma unroll 4
        for (int s = 0; s < CHLEN; s++) {
            float f = gp[0], o = gp[256], z = gp[512];
            c = f * c + (1.f - f) * z;
            float h = c * o;
            *op = h;
            if (s == 0) { h_first = h; c_first = c; }
            gp -= N_TOT;
            op -= 512;
        }
        if (ch == NCH - 1) {   // processed l = 4095 first
            out[OUT_HL + b * 512 + 256 + d]        = h_first;
            out[OUT_HL + 4096 + b * 512 + 256 + d] = c_first;
        }
    }
}

// ---------------------------------------------------------------------------
extern "C" void kernel_launch(void* const* d_in, const int* in_sizes, int n_in,
                              void* d_out, int out_size) {
    const float* x  = (const float*)d_in[0];
    const float* Wf = (const float*)d_in[2];
    const float* bf = (const float*)d_in[3];
    const float* Wb = (const float*)d_in[4];
    const float* bb = (const float*)d_in[5];
    float* out = (float*)d_out;

    cudaFuncSetAttribute(gemm_hmma, cudaFuncAttributeMaxDynamicSharedMemorySize, GEMM_SMEM);

    {
        int tot8 = BATCH * LP * DIN / 8;
        prep_x<<<(tot8 + 255) / 256, 256>>>(x);
    }
    {
        int tot = N_TOT * K_TOT;
        prep_w<<<(tot + 255) / 256, 256>>>(Wf, Wb);
    }
    gemm_hmma<<<dim3(12, 128), 256, GEMM_SMEM>>>(bf, bb);
    scanA<<<1024, 256>>>();
    scanB<<<16, 256>>>();
    scanC<<<1024, 256>>>(out);
}

// round 4
// speedup vs baseline: 4.0149x; 1.5329x over previous
#include <cuda_runtime.h>
#include <cuda_fp16.h>
#include <stdint.h>
#include <math.h>

#define BATCH 8
#define LSEQ  4096
#define DIN   256
#define M_TOT 32768
#define N_TOT 1536
#define K_TOT 768
#define LP    4098   // padded rows per batch (one zero row each side)

// ---------------- scratch (static device globals) ----------------
__device__ __align__(16) __half g_xh[BATCH * LP * DIN];
__device__ __align__(16) __half g_wh[N_TOT * K_TOT];
__device__ __align__(16) __half g_wl[N_TOT * K_TOT];
__device__ float g_gates[(size_t)M_TOT * N_TOT];
// chunked-scan scratch: [dir][b][chunk][d]
#define NCH 64
#define CHLEN 64
__device__ float g_F[2 * BATCH * NCH * 256];
__device__ float g_Cz[2 * BATCH * NCH * 256];
__device__ float g_init[2 * BATCH * NCH * 256];

// ---------------- PTX helpers (arch-agnostic, compute_80-era) ----------------
__device__ __forceinline__ uint32_t smem_u32(const void* p) {
    uint32_t a;
    asm("{ .reg .u64 t; cvta.to.shared.u64 t, %1; cvt.u32.u64 %0, t; }" : "=r"(a) : "l"(p));
    return a;
}
__device__ __forceinline__ void cp16(uint32_t dst, const void* src) {
    asm volatile("cp.async.cg.shared.global [%0], [%1], 16;" :: "r"(dst), "l"(src));
}
__device__ __forceinline__ void cp_commit() {
    asm volatile("cp.async.commit_group;" ::: "memory");
}
template<int N> __device__ __forceinline__ void cp_wait() {
    asm volatile("cp.async.wait_group %0;" :: "n"(N) : "memory");
}
__device__ __forceinline__ void ldsm4(uint32_t* r, uint32_t addr) {
    asm volatile("ldmatrix.sync.aligned.m8n8.x4.shared.b16 {%0,%1,%2,%3}, [%4];"
                 : "=r"(r[0]), "=r"(r[1]), "=r"(r[2]), "=r"(r[3]) : "r"(addr));
}
__device__ __forceinline__ void mma_f16(float* d, const uint32_t* a, uint32_t b0, uint32_t b1) {
    asm volatile("mma.sync.aligned.m16n8k16.row.col.f32.f16.f16.f32 "
                 "{%0,%1,%2,%3}, {%4,%5,%6,%7}, {%8,%9}, {%0,%1,%2,%3};"
                 : "+f"(d[0]), "+f"(d[1]), "+f"(d[2]), "+f"(d[3])
                 : "r"(a[0]), "r"(a[1]), "r"(a[2]), "r"(a[3]), "r"(b0), "r"(b1));
}

// ---------------------------------------------------------------------------
// Kernel 1: convert + pad x -> fp16  (rows: b*(L+2) + (l+1))
// ---------------------------------------------------------------------------
__global__ void prep_x(const float* __restrict__ x) {
    int idx = blockIdx.x * blockDim.x + threadIdx.x;
    const int TOT8 = BATCH * LP * DIN / 8;
    if (idx >= TOT8) return;
    int e0 = idx * 8;
    int b = e0 / (LP * DIN);
    int rem = e0 - b * LP * DIN;
    int r = rem / DIN;
    int i = rem - r * DIN;
    int l = r - 1;
    float v[8];
    if (l >= 0 && l < LSEQ) {
        const float4* src = (const float4*)(x + ((size_t)(b * LSEQ + l)) * DIN + i);
        float4 a = src[0], c = src[1];
        v[0]=a.x; v[1]=a.y; v[2]=a.z; v[3]=a.w; v[4]=c.x; v[5]=c.y; v[6]=c.z; v[7]=c.w;
    } else {
#pragma unroll
        for (int j = 0; j < 8; j++) v[j] = 0.f;
    }
    __half h[8];
#pragma unroll
    for (int j = 0; j < 8; j++) h[j] = __float2half_rn(v[j]);
    *(uint4*)(g_xh + e0) = *(uint4*)h;
}

// ---------------------------------------------------------------------------
// Kernel 2: weights -> [c][kk=tap*256+i] fp16 hi/lo (exact 2-term split)
// ---------------------------------------------------------------------------
__global__ void prep_w(const float* __restrict__ Wf, const float* __restrict__ Wb) {
    int idx = blockIdx.x * blockDim.x + threadIdx.x;
    if (idx >= N_TOT * K_TOT) return;
    int c = idx / K_TOT;
    int kk = idx - c * K_TOT;
    int tap = kk >> 8;
    int i = kk & 255;
    float v = (c < 768) ? Wf[c * 768 + i * 3 + tap] : Wb[(c - 768) * 768 + i * 3 + tap];
    __half hi = __float2half_rn(v);
    g_wh[idx] = hi;
    g_wl[idx] = __float2half_rn(v - __half2float(hi));
}

// ---------------------------------------------------------------------------
// Kernel 3: fp16 2-term HMMA GEMM + bias + activation -> g_gates
// BM=256, BN=128, BK=32, 256 threads, warp tile 64x64, 4-stage cp.async
// 24 k-chunk iterations; per chunk: acc += A_h*B_h + A_h*B_l
// ---------------------------------------------------------------------------
#define STAGES 4
#define STAGE_BYTES 32768     // A: 256*64B = 16384, B_h: 8192, B_l: 8192
#define GEMM_SMEM (STAGES * STAGE_BYTES)
#define NIT 24

__device__ __forceinline__ float actv(float v, int ctype) {
    if (ctype == 2) {
        float t = __expf(-2.f * fabsf(v));
        float r = (1.f - t) / (1.f + t);
        return copysignf(r, v);
    }
    return 1.f / (1.f + __expf(-v));
}

__device__ __forceinline__ void gemm_issue(uint32_t smemU, int stage, int kchunk,
                                           int rbase, int n0, int tid) {
    int kc = kchunk * 32;
    int tap = kc >> 8;
    int i0 = kc & 255;
    uint32_t abase = smemU + stage * STAGE_BYTES;
    uint32_t bhbase = abase + 16384;
    uint32_t blbase = abase + 24576;
#pragma unroll
    for (int q = 0; q < 4; q++) {
        int idx = tid + q * 256;
        int row = idx >> 2, c16 = idx & 3;
        int chunk = c16 ^ (row & 3) ^ ((row >> 2) & 1);
        cp16(abase + row * 64 + chunk * 16,
             g_xh + (size_t)(rbase + tap + row) * 256 + i0 + c16 * 8);
    }
#pragma unroll
    for (int q = 0; q < 2; q++) {
        int idx = tid + q * 256;
        int row = idx >> 2, c16 = idx & 3;
        int chunk = c16 ^ (row & 3) ^ ((row >> 2) & 1);
        size_t wsrc = (size_t)(n0 + row) * 768 + kc + c16 * 8;
        cp16(bhbase + row * 64 + chunk * 16, g_wh + wsrc);
        cp16(blbase + row * 64 + chunk * 16, g_wl + wsrc);
    }
}

__global__ __launch_bounds__(256, 1)
void gemm_hmma(const float* __restrict__ bfv, const float* __restrict__ bbv) {
    extern __shared__ char smem[];
    uint32_t smemU = smem_u32(smem);
    const int tid = threadIdx.x;
    const int lane = tid & 31;
    const int w = tid >> 5;
    const int wm = w >> 1;          // 0..3
    const int wn = w & 1;           // 0..1
    const int n0 = blockIdx.x * 128;
    const int m0 = blockIdx.y * 256;
    const int batch = m0 >> 12;
    const int l0 = m0 & 4095;
    const int rbase = batch * LP + l0;

    // per-thread ldmatrix read offsets (within a stage)
    const int lr = lane & 7;
    const int grp = lane >> 3;
    const int arow = wm * 64 + (grp & 1) * 8 + lr;
    const int achk = (grp >> 1) ^ (arow & 3) ^ ((arow >> 2) & 1);
    const uint32_t aoff0 = (uint32_t)(arow * 64 + achk * 16);
    const int brow = wn * 64 + (grp >> 1) * 8 + lr;
    const int bchk = (grp & 1) ^ (brow & 3) ^ ((brow >> 2) & 1);
    const uint32_t boff0 = (uint32_t)(16384 + brow * 64 + bchk * 16);

    float acc[4][8][4];
#pragma unroll
    for (int mt = 0; mt < 4; mt++)
#pragma unroll
        for (int nt = 0; nt < 8; nt++)
#pragma unroll
            for (int r = 0; r < 4; r++) acc[mt][nt][r] = 0.f;

    // prologue: fill 3 stages
#pragma unroll
    for (int s = 0; s < STAGES - 1; s++) {
        gemm_issue(smemU, s, s, rbase, n0, tid);
        cp_commit();
    }

#pragma unroll 1
    for (int j = 0; j < NIT; j++) {
        cp_wait<STAGES - 2>();
        __syncthreads();
        if (j + STAGES - 1 < NIT)
            gemm_issue(smemU, (j + STAGES - 1) & (STAGES - 1), j + STAGES - 1, rbase, n0, tid);
        cp_commit();

        uint32_t stbase = smemU + (j & (STAGES - 1)) * STAGE_BYTES;
#pragma unroll
        for (int ks = 0; ks < 2; ks++) {
            uint32_t a[4][4], bh[4][4], bl[4][4];
#pragma unroll
            for (int mt = 0; mt < 4; mt++)
                ldsm4(a[mt], (stbase + aoff0 + mt * 1024) ^ (ks * 32));
#pragma unroll
            for (int np = 0; np < 4; np++) {
                ldsm4(bh[np], (stbase + boff0 + np * 1024) ^ (ks * 32));
                ldsm4(bl[np], (stbase + boff0 + 8192 + np * 1024) ^ (ks * 32));
            }
#pragma unroll
            for (int mt = 0; mt < 4; mt++)
#pragma unroll
                for (int nt = 0; nt < 8; nt++) {
                    mma_f16(acc[mt][nt], a[mt], bh[nt >> 1][(nt & 1) * 2], bh[nt >> 1][(nt & 1) * 2 + 1]);
                    mma_f16(acc[mt][nt], a[mt], bl[nt >> 1][(nt & 1) * 2], bl[nt >> 1][(nt & 1) * 2 + 1]);
                }
        }
    }

    // epilogue: bias + activation
    const int ctype = (n0 >> 8) % 3;
    const float* bsrc = (n0 < 768) ? bfv : bbv;
    const int cofs = (n0 < 768) ? n0 : (n0 - 768);

#pragma unroll
    for (int mt = 0; mt < 4; mt++) {
        int mrow = m0 + wm * 64 + mt * 16 + (lane >> 2);
        float* d0 = g_gates + (size_t)mrow * N_TOT + n0;
        float* d1 = d0 + (size_t)8 * N_TOT;
#pragma unroll
        for (int nt = 0; nt < 8; nt++) {
            int cc = wn * 64 + nt * 8 + (lane & 3) * 2;
            float bb0 = bsrc[cofs + cc];
            float bb1 = bsrc[cofs + cc + 1];
            float2 v0, v1;
            v0.x = actv(acc[mt][nt][0] + bb0, ctype);
            v0.y = actv(acc[mt][nt][1] + bb1, ctype);
            v1.x = actv(acc[mt][nt][2] + bb0, ctype);
            v1.y = actv(acc[mt][nt][3] + bb1, ctype);
            *(float2*)(d0 + cc) = v0;
            *(float2*)(d1 + cc) = v1;
        }
    }
}

// ---------------------------------------------------------------------------
// Chunked bidirectional fo-pool scan
// ---------------------------------------------------------------------------
__global__ void scanA() {
    int bid = blockIdx.x;
    int dir = bid >> 9;
    int rem = bid & 511;
    int b = rem >> 6;
    int ch = rem & 63;
    int d = threadIdx.x;

    float F = 1.f, c = 0.f;
    if (dir == 0) {
        const float* gp = g_gates + (size_t)(b * LSEQ + ch * CHLEN) * N_TOT + d;
#pragma unroll 4
        for (int s = 0; s < CHLEN; s++) {
            float f = gp[0], z = gp[512];
            c = f * c + (1.f - f) * z;
            F *= f;
            gp += N_TOT;
        }
    } else {
        const float* gp = g_gates + (size_t)(b * LSEQ + ch * CHLEN + CHLEN - 1) * N_TOT + 768 + d;
#pragma unroll 4
        for (int s = 0; s < CHLEN; s++) {
            float f = gp[0], z = gp[512];
            c = f * c + (1.f - f) * z;
            F *= f;
            gp -= N_TOT;
        }
    }
    int idx = ((dir * BATCH + b) * NCH + ch) * 256 + d;
    g_F[idx] = F;
    g_Cz[idx] = c;
}

__global__ void scanB() {
    int dir = blockIdx.x >> 3;
    int b = blockIdx.x & 7;
    int d = threadIdx.x;
    float c = 0.f;
    if (dir == 0) {
        for (int ch = 0; ch < NCH; ch++) {
            int idx = ((b) * NCH + ch) * 256 + d;
            g_init[idx] = c;
            c = g_F[idx] * c + g_Cz[idx];
        }
    } else {
        for (int ch = NCH - 1; ch >= 0; ch--) {
            int idx = ((BATCH + b) * NCH + ch) * 256 + d;
            g_init[idx] = c;
            c = g_F[idx] * c + g_Cz[idx];
        }
    }
}

__global__ void scanC(float* __restrict__ out) {
    int bid = blockIdx.x;
    int dir = bid >> 9;
    int rem = bid & 511;
    int b = rem >> 6;
    int ch = rem & 63;
    int d = threadIdx.x;
    const size_t OUT_HL = (size_t)BATCH * LSEQ * 512;

    float c = g_init[((dir * BATCH + b) * NCH + ch) * 256 + d];
    if (dir == 0) {
        const float* gp = g_gates + (size_t)(b * LSEQ + ch * CHLEN) * N_TOT + d;
        float* op = out + (size_t)(b * LSEQ + ch * CHLEN) * 512 + d;
        float h = 0.f;
#pragma unroll 4
        for (int s = 0; s < CHLEN; s++) {
            float f = gp[0], o = gp[256], z = gp[512];
            c = f * c + (1.f - f) * z;
            h = c * o;
            *op = h;
            gp += N_TOT;
            op += 512;
        }
        if (ch == NCH - 1) {
            out[OUT_HL + b * 512 + d]        = h;
            out[OUT_HL + 4096 + b * 512 + d] = c;
        }
    } else {
        const float* gp = g_gates + (size_t)(b * LSEQ + ch * CHLEN + CHLEN - 1) * N_TOT + 768 + d;
        float* op = out + (size_t)(b * LSEQ + ch * CHLEN + CHLEN - 1) * 512 + 256 + d;
        float h_first = 0.f, c_first = 0.f;
#pragma unroll 4
        for (int s = 0; s < CHLEN; s++) {
            float f = gp[0], o = gp[256], z = gp[512];
            c = f * c + (1.f - f) * z;
            float h = c * o;
            *op = h;
            if (s == 0) { h_first = h; c_first = c; }
            gp -= N_TOT;
            op -= 512;
        }
        if (ch == NCH - 1) {   // processed l = 4095 first
            out[OUT_HL + b * 512 + 256 + d]        = h_first;
            out[OUT_HL + 4096 + b * 512 + 256 + d] = c_first;
        }
    }
}

// ---------------------------------------------------------------------------
extern "C" void kernel_launch(void* const* d_in, const int* in_sizes, int n_in,
                              void* d_out, int out_size) {
    const float* x  = (const float*)d_in[0];
    const float* Wf = (const float*)d_in[2];
    const float* bf = (const float*)d_in[3];
    const float* Wb = (const float*)d_in[4];
    const float* bb = (const float*)d_in[5];
    float* out = (float*)d_out;

    cudaFuncSetAttribute(gemm_hmma, cudaFuncAttributeMaxDynamicSharedMemorySize, GEMM_SMEM);

    {
        int tot8 = BATCH * LP * DIN / 8;
        prep_x<<<(tot8 + 255) / 256, 256>>>(x);
    }
    {
        int tot = N_TOT * K_TOT;
        prep_w<<<(tot + 255) / 256, 256>>>(Wf, Wb);
    }
    gemm_hmma<<<dim3(12, 128), 256, GEMM_SMEM>>>(bf, bb);
    scanA<<<1024, 256>>>();
    scanB<<<16, 256>>>();
    scanC<<<1024, 256>>>(out);
}

// round 5
// speedup vs baseline: 5.5799x; 1.3898x over previous
#include <cuda_runtime.h>
#include <cuda_fp16.h>
#include <stdint.h>
#include <math.h>

#define BATCH 8
#define LSEQ  4096
#define DIN   256
#define M_TOT 32768
#define N_TOT 1536
#define K_TOT 768
#define LP    4098   // padded rows per batch (one zero row each side)

// ---------------- scratch (static device globals) ----------------
__device__ __align__(16) __half g_xh[BATCH * LP * DIN];
__device__ __align__(16) __half g_wh[N_TOT * K_TOT];
__device__ __align__(16) __half g_gates[(size_t)M_TOT * N_TOT];   // fp16 activated gates (~100MB)
// chunked-scan scratch: [dir][b][chunk][d]
#define NCH 64
#define CHLEN 64
__device__ float g_F[2 * BATCH * NCH * 256];
__device__ float g_Cz[2 * BATCH * NCH * 256];
__device__ float g_init[2 * BATCH * NCH * 256];

// ---------------- PTX helpers (arch-agnostic, compute_80-era) ----------------
__device__ __forceinline__ uint32_t smem_u32(const void* p) {
    uint32_t a;
    asm("{ .reg .u64 t; cvta.to.shared.u64 t, %1; cvt.u32.u64 %0, t; }" : "=r"(a) : "l"(p));
    return a;
}
__device__ __forceinline__ void cp16(uint32_t dst, const void* src) {
    asm volatile("cp.async.cg.shared.global [%0], [%1], 16;" :: "r"(dst), "l"(src));
}
__device__ __forceinline__ void cp_commit() {
    asm volatile("cp.async.commit_group;" ::: "memory");
}
template<int N> __device__ __forceinline__ void cp_wait() {
    asm volatile("cp.async.wait_group %0;" :: "n"(N) : "memory");
}
__device__ __forceinline__ void ldsm4(uint32_t* r, uint32_t addr) {
    asm volatile("ldmatrix.sync.aligned.m8n8.x4.shared.b16 {%0,%1,%2,%3}, [%4];"
                 : "=r"(r[0]), "=r"(r[1]), "=r"(r[2]), "=r"(r[3]) : "r"(addr));
}
__device__ __forceinline__ void mma_f16(float* d, const uint32_t* a, uint32_t b0, uint32_t b1) {
    asm volatile("mma.sync.aligned.m16n8k16.row.col.f32.f16.f16.f32 "
                 "{%0,%1,%2,%3}, {%4,%5,%6,%7}, {%8,%9}, {%0,%1,%2,%3};"
                 : "+f"(d[0]), "+f"(d[1]), "+f"(d[2]), "+f"(d[3])
                 : "r"(a[0]), "r"(a[1]), "r"(a[2]), "r"(a[3]), "r"(b0), "r"(b1));
}

// ---------------------------------------------------------------------------
// Kernel 1: convert + pad x -> fp16  (rows: b*(L+2) + (l+1))
// ---------------------------------------------------------------------------
__global__ void prep_x(const float* __restrict__ x) {
    int idx = blockIdx.x * blockDim.x + threadIdx.x;
    const int TOT8 = BATCH * LP * DIN / 8;
    if (idx >= TOT8) return;
    int e0 = idx * 8;
    int b = e0 / (LP * DIN);
    int rem = e0 - b * LP * DIN;
    int r = rem / DIN;
    int i = rem - r * DIN;
    int l = r - 1;
    float v[8];
    if (l >= 0 && l < LSEQ) {
        const float4* src = (const float4*)(x + ((size_t)(b * LSEQ + l)) * DIN + i);
        float4 a = src[0], c = src[1];
        v[0]=a.x; v[1]=a.y; v[2]=a.z; v[3]=a.w; v[4]=c.x; v[5]=c.y; v[6]=c.z; v[7]=c.w;
    } else {
#pragma unroll
        for (int j = 0; j < 8; j++) v[j] = 0.f;
    }
    __half h[8];
#pragma unroll
    for (int j = 0; j < 8; j++) h[j] = __float2half_rn(v[j]);
    *(uint4*)(g_xh + e0) = *(uint4*)h;
}

// ---------------------------------------------------------------------------
// Kernel 2: weights -> [c][kk=tap*256+i] fp16
// ---------------------------------------------------------------------------
__global__ void prep_w(const float* __restrict__ Wf, const float* __restrict__ Wb) {
    int idx = blockIdx.x * blockDim.x + threadIdx.x;
    if (idx >= N_TOT * K_TOT) return;
    int c = idx / K_TOT;
    int kk = idx - c * K_TOT;
    int tap = kk >> 8;
    int i = kk & 255;
    float v = (c < 768) ? Wf[c * 768 + i * 3 + tap] : Wb[(c - 768) * 768 + i * 3 + tap];
    g_wh[idx] = __float2half_rn(v);
}

// ---------------------------------------------------------------------------
// Kernel 3: fp16 HMMA GEMM + bias + activation -> g_gates (fp16)
// BM=256, BN=128, BK=32, 256 threads, warp tile 64x64, 4-stage cp.async
// ---------------------------------------------------------------------------
#define STAGES 4
#define STAGE_BYTES 24576     // A: 256*64B = 16384, B: 128*64B = 8192
#define GEMM_SMEM (STAGES * STAGE_BYTES)
#define NIT 24

__device__ __forceinline__ float actv(float v, int ctype) {
    if (ctype == 2) {
        float t = __expf(-2.f * fabsf(v));
        float r = (1.f - t) / (1.f + t);
        return copysignf(r, v);
    }
    return 1.f / (1.f + __expf(-v));
}

__device__ __forceinline__ void gemm_issue(uint32_t smemU, int stage, int kchunk,
                                           int rbase, int n0, int tid) {
    int kc = kchunk * 32;
    int tap = kc >> 8;
    int i0 = kc & 255;
    uint32_t abase = smemU + stage * STAGE_BYTES;
    uint32_t bbase = abase + 16384;
#pragma unroll
    for (int q = 0; q < 4; q++) {
        int idx = tid + q * 256;
        int row = idx >> 2, c16 = idx & 3;
        int chunk = c16 ^ (row & 3) ^ ((row >> 2) & 1);
        cp16(abase + row * 64 + chunk * 16,
             g_xh + (size_t)(rbase + tap + row) * 256 + i0 + c16 * 8);
    }
#pragma unroll
    for (int q = 0; q < 2; q++) {
        int idx = tid + q * 256;
        int row = idx >> 2, c16 = idx & 3;
        int chunk = c16 ^ (row & 3) ^ ((row >> 2) & 1);
        cp16(bbase + row * 64 + chunk * 16,
             g_wh + (size_t)(n0 + row) * 768 + kc + c16 * 8);
    }
}

__global__ __launch_bounds__(256, 1)
void gemm_hmma(const float* __restrict__ bfv, const float* __restrict__ bbv) {
    extern __shared__ char smem[];
    uint32_t smemU = smem_u32(smem);
    const int tid = threadIdx.x;
    const int lane = tid & 31;
    const int w = tid >> 5;
    const int wm = w >> 1;          // 0..3
    const int wn = w & 1;           // 0..1
    const int n0 = blockIdx.x * 128;
    const int m0 = blockIdx.y * 256;
    const int batch = m0 >> 12;
    const int l0 = m0 & 4095;
    const int rbase = batch * LP + l0;

    // per-thread ldmatrix read offsets (within a stage)
    const int lr = lane & 7;
    const int grp = lane >> 3;
    const int arow = wm * 64 + (grp & 1) * 8 + lr;
    const int achk = (grp >> 1) ^ (arow & 3) ^ ((arow >> 2) & 1);
    const uint32_t aoff0 = (uint32_t)(arow * 64 + achk * 16);
    const int brow = wn * 64 + (grp >> 1) * 8 + lr;
    const int bchk = (grp & 1) ^ (brow & 3) ^ ((brow >> 2) & 1);
    const uint32_t boff0 = (uint32_t)(16384 + brow * 64 + bchk * 16);

    float acc[4][8][4];
#pragma unroll
    for (int mt = 0; mt < 4; mt++)
#pragma unroll
        for (int nt = 0; nt < 8; nt++)
#pragma unroll
            for (int r = 0; r < 4; r++) acc[mt][nt][r] = 0.f;

    // prologue: fill 3 stages
#pragma unroll
    for (int s = 0; s < STAGES - 1; s++) {
        gemm_issue(smemU, s, s, rbase, n0, tid);
        cp_commit();
    }

#pragma unroll 1
    for (int j = 0; j < NIT; j++) {
        cp_wait<STAGES - 2>();
        __syncthreads();
        if (j + STAGES - 1 < NIT)
            gemm_issue(smemU, (j + STAGES - 1) & (STAGES - 1), j + STAGES - 1, rbase, n0, tid);
        cp_commit();

        uint32_t stbase = smemU + (j & (STAGES - 1)) * STAGE_BYTES;
#pragma unroll
        for (int ks = 0; ks < 2; ks++) {
            uint32_t a[4][4], b[4][4];
#pragma unroll
            for (int mt = 0; mt < 4; mt++)
                ldsm4(a[mt], (stbase + aoff0 + mt * 1024) ^ (ks * 32));
#pragma unroll
            for (int np = 0; np < 4; np++)
                ldsm4(b[np], (stbase + boff0 + np * 1024) ^ (ks * 32));
#pragma unroll
            for (int mt = 0; mt < 4; mt++)
#pragma unroll
                for (int nt = 0; nt < 8; nt++)
                    mma_f16(acc[mt][nt], a[mt], b[nt >> 1][(nt & 1) * 2], b[nt >> 1][(nt & 1) * 2 + 1]);
        }
    }

    // epilogue: bias + activation -> fp16 gates
    const int ctype = (n0 >> 8) % 3;
    const float* bsrc = (n0 < 768) ? bfv : bbv;
    const int cofs = (n0 < 768) ? n0 : (n0 - 768);

#pragma unroll
    for (int mt = 0; mt < 4; mt++) {
        int mrow = m0 + wm * 64 + mt * 16 + (lane >> 2);
        __half* d0 = g_gates + (size_t)mrow * N_TOT + n0;
        __half* d1 = d0 + (size_t)8 * N_TOT;
#pragma unroll
        for (int nt = 0; nt < 8; nt++) {
            int cc = wn * 64 + nt * 8 + (lane & 3) * 2;
            float bb0 = bsrc[cofs + cc];
            float bb1 = bsrc[cofs + cc + 1];
            __half2 v0, v1;
            v0.x = __float2half_rn(actv(acc[mt][nt][0] + bb0, ctype));
            v0.y = __float2half_rn(actv(acc[mt][nt][1] + bb1, ctype));
            v1.x = __float2half_rn(actv(acc[mt][nt][2] + bb0, ctype));
            v1.y = __float2half_rn(actv(acc[mt][nt][3] + bb1, ctype));
            *(__half2*)(d0 + cc) = v0;
            *(__half2*)(d1 + cc) = v1;
        }
    }
}

// ---------------------------------------------------------------------------
// Chunked bidirectional fo-pool scan (fp16 gates, fp32 state)
// ---------------------------------------------------------------------------
__global__ void scanA() {
    int bid = blockIdx.x;
    int dir = bid >> 9;
    int rem = bid & 511;
    int b = rem >> 6;
    int ch = rem & 63;
    int d = threadIdx.x;

    float F = 1.f, c = 0.f;
    if (dir == 0) {
        const __half* gp = g_gates + (size_t)(b * LSEQ + ch * CHLEN) * N_TOT + d;
#pragma unroll 4
        for (int s = 0; s < CHLEN; s++) {
            float f = __half2float(gp[0]), z = __half2float(gp[512]);
            c = f * c + (1.f - f) * z;
            F *= f;
            gp += N_TOT;
        }
    } else {
        const __half* gp = g_gates + (size_t)(b * LSEQ + ch * CHLEN + CHLEN - 1) * N_TOT + 768 + d;
#pragma unroll 4
        for (int s = 0; s < CHLEN; s++) {
            float f = __half2float(gp[0]), z = __half2float(gp[512]);
            c = f * c + (1.f - f) * z;
            F *= f;
            gp -= N_TOT;
        }
    }
    int idx = ((dir * BATCH + b) * NCH + ch) * 256 + d;
    g_F[idx] = F;
    g_Cz[idx] = c;
}

__global__ void scanB() {
    int dir = blockIdx.x >> 3;
    int b = blockIdx.x & 7;
    int d = threadIdx.x;
    float c = 0.f;
    if (dir == 0) {
        for (int ch = 0; ch < NCH; ch++) {
            int idx = ((b) * NCH + ch) * 256 + d;
            g_init[idx] = c;
            c = g_F[idx] * c + g_Cz[idx];
        }
    } else {
        for (int ch = NCH - 1; ch >= 0; ch--) {
            int idx = ((BATCH + b) * NCH + ch) * 256 + d;
            g_init[idx] = c;
            c = g_F[idx] * c + g_Cz[idx];
        }
    }
}

__global__ void scanC(float* __restrict__ out) {
    int bid = blockIdx.x;
    int dir = bid >> 9;
    int rem = bid & 511;
    int b = rem >> 6;
    int ch = rem & 63;
    int d = threadIdx.x;
    const size_t OUT_HL = (size_t)BATCH * LSEQ * 512;

    float c = g_init[((dir * BATCH + b) * NCH + ch) * 256 + d];
    if (dir == 0) {
        const __half* gp = g_gates + (size_t)(b * LSEQ + ch * CHLEN) * N_TOT + d;
        float* op = out + (size_t)(b * LSEQ + ch * CHLEN) * 512 + d;
        float h = 0.f;
#pragma unroll 4
        for (int s = 0; s < CHLEN; s++) {
            float f = __half2float(gp[0]), o = __half2float(gp[256]), z = __half2float(gp[512]);
            c = f * c + (1.f - f) * z;
            h = c * o;
            *op = h;
            gp += N_TOT;
            op += 512;
        }
        if (ch == NCH - 1) {
            out[OUT_HL + b * 512 + d]        = h;
            out[OUT_HL + 4096 + b * 512 + d] = c;
        }
    } else {
        const __half* gp = g_gates + (size_t)(b * LSEQ + ch * CHLEN + CHLEN - 1) * N_TOT + 768 + d;
        float* op = out + (size_t)(b * LSEQ + ch * CHLEN + CHLEN - 1) * 512 + 256 + d;
        float h_first = 0.f, c_first = 0.f;
#pragma unroll 4
        for (int s = 0; s < CHLEN; s++) {
            float f = __half2float(gp[0]), o = __half2float(gp[256]), z = __half2float(gp[512]);
            c = f * c + (1.f - f) * z;
            float h = c * o;
            *op = h;
            if (s == 0) { h_first = h; c_first = c; }
            gp -= N_TOT;
            op -= 512;
        }
        if (ch == NCH - 1) {   // processed l = 4095 first
            out[OUT_HL + b * 512 + 256 + d]        = h_first;
            out[OUT_HL + 4096 + b * 512 + 256 + d] = c_first;
        }
    }
}

// ---------------------------------------------------------------------------
extern "C" void kernel_launch(void* const* d_in, const int* in_sizes, int n_in,
                              void* d_out, int out_size) {
    const float* x  = (const float*)d_in[0];
    const float* Wf = (const float*)d_in[2];
    const float* bf = (const float*)d_in[3];
    const float* Wb = (const float*)d_in[4];
    const float* bb = (const float*)d_in[5];
    float* out = (float*)d_out;

    cudaFuncSetAttribute(gemm_hmma, cudaFuncAttributeMaxDynamicSharedMemorySize, GEMM_SMEM);

    {
        int tot8 = BATCH * LP * DIN / 8;
        prep_x<<<(tot8 + 255) / 256, 256>>>(x);
    }
    {
        int tot = N_TOT * K_TOT;
        prep_w<<<(tot + 255) / 256, 256>>>(Wf, Wb);
    }
    gemm_hmma<<<dim3(12, 128), 256, GEMM_SMEM>>>(bf, bb);
    scanA<<<1024, 256>>>();
    scanB<<<16, 256>>>();
    scanC<<<1024, 256>>>(out);
}

// round 6
// speedup vs baseline: 7.1287x; 1.2776x over previous
#include <cuda_runtime.h>
#include <cuda_fp16.h>
#include <stdint.h>
#include <math.h>

#define BATCH 8
#define LSEQ  4096
#define DIN   256
#define M_TOT 32768
#define N_TOT 1536
#define K_TOT 768
#define LP    4098   // padded rows per batch (one zero row each side)

// ---------------- scratch (static device globals) ----------------
__device__ __align__(16) __half g_xh[BATCH * LP * DIN];
__device__ __align__(16) __half g_wh[N_TOT * K_TOT];
__device__ __align__(16) __half g_gates[(size_t)M_TOT * N_TOT];   // fp16 activated gates (~100MB)
// chunked-scan scratch: [dir][b][chunk][d]
#define NCH 64
#define CHLEN 64
__device__ float g_F[2 * BATCH * NCH * 256];
__device__ float g_Cz[2 * BATCH * NCH * 256];
__device__ float g_init[2 * BATCH * NCH * 256];

// ---------------- PTX helpers (arch-agnostic, compute_80-era) ----------------
__device__ __forceinline__ uint32_t smem_u32(const void* p) {
    uint32_t a;
    asm("{ .reg .u64 t; cvta.to.shared.u64 t, %1; cvt.u32.u64 %0, t; }" : "=r"(a) : "l"(p));
    return a;
}
__device__ __forceinline__ void cp16(uint32_t dst, const void* src) {
    asm volatile("cp.async.cg.shared.global [%0], [%1], 16;" :: "r"(dst), "l"(src));
}
__device__ __forceinline__ void cp_commit() {
    asm volatile("cp.async.commit_group;" ::: "memory");
}
template<int N> __device__ __forceinline__ void cp_wait() {
    asm volatile("cp.async.wait_group %0;" :: "n"(N) : "memory");
}
__device__ __forceinline__ void ldsm4(uint32_t* r, uint32_t addr) {
    asm volatile("ldmatrix.sync.aligned.m8n8.x4.shared.b16 {%0,%1,%2,%3}, [%4];"
                 : "=r"(r[0]), "=r"(r[1]), "=r"(r[2]), "=r"(r[3]) : "r"(addr));
}
__device__ __forceinline__ void mma_f16(float* d, const uint32_t* a, uint32_t b0, uint32_t b1) {
    asm volatile("mma.sync.aligned.m16n8k16.row.col.f32.f16.f16.f32 "
                 "{%0,%1,%2,%3}, {%4,%5,%6,%7}, {%8,%9}, {%0,%1,%2,%3};"
                 : "+f"(d[0]), "+f"(d[1]), "+f"(d[2]), "+f"(d[3])
                 : "r"(a[0]), "r"(a[1]), "r"(a[2]), "r"(a[3]), "r"(b0), "r"(b1));
}

// ---------------------------------------------------------------------------
// Kernel 1: convert + pad x -> fp16  (rows: b*(L+2) + (l+1))
// ---------------------------------------------------------------------------
__global__ void prep_x(const float* __restrict__ x) {
    int idx = blockIdx.x * blockDim.x + threadIdx.x;
    const int TOT8 = BATCH * LP * DIN / 8;
    if (idx >= TOT8) return;
    int e0 = idx * 8;
    int b = e0 / (LP * DIN);
    int rem = e0 - b * LP * DIN;
    int r = rem / DIN;
    int i = rem - r * DIN;
    int l = r - 1;
    float v[8];
    if (l >= 0 && l < LSEQ) {
        const float4* src = (const float4*)(x + ((size_t)(b * LSEQ + l)) * DIN + i);
        float4 a = src[0], c = src[1];
        v[0]=a.x; v[1]=a.y; v[2]=a.z; v[3]=a.w; v[4]=c.x; v[5]=c.y; v[6]=c.z; v[7]=c.w;
    } else {
#pragma unroll
        for (int j = 0; j < 8; j++) v[j] = 0.f;
    }
    __half h[8];
#pragma unroll
    for (int j = 0; j < 8; j++) h[j] = __float2half_rn(v[j]);
    *(uint4*)(g_xh + e0) = *(uint4*)h;
}

// ---------------------------------------------------------------------------
// Kernel 2: weights -> [c][kk=tap*256+i] fp16
// ---------------------------------------------------------------------------
__global__ void prep_w(const float* __restrict__ Wf, const float* __restrict__ Wb) {
    int idx = blockIdx.x * blockDim.x + threadIdx.x;
    if (idx >= N_TOT * K_TOT) return;
    int c = idx / K_TOT;
    int kk = idx - c * K_TOT;
    int tap = kk >> 8;
    int i = kk & 255;
    float v = (c < 768) ? Wf[c * 768 + i * 3 + tap] : Wb[(c - 768) * 768 + i * 3 + tap];
    g_wh[idx] = __float2half_rn(v);
}

// ---------------------------------------------------------------------------
// Kernel 3: fp16 HMMA GEMM + bias + activation -> g_gates (fp16)
// BM=128, BN=128, BK=32, 256 threads, warp tile 32x64, 4-stage cp.async
// 2 CTAs/SM for bubble overlap
// ---------------------------------------------------------------------------
#define STAGES 4
#define STAGE_BYTES 16384     // A: 128*64B = 8192, B: 128*64B = 8192
#define GEMM_SMEM (STAGES * STAGE_BYTES)
#define NIT 24

__device__ __forceinline__ float actv(float v, int ctype) {
    if (ctype == 2) {
        float t = __expf(-2.f * fabsf(v));
        float r = (1.f - t) / (1.f + t);
        return copysignf(r, v);
    }
    return 1.f / (1.f + __expf(-v));
}

__device__ __forceinline__ void gemm_issue(uint32_t smemU, int stage, int kchunk,
                                           int rbase, int n0, int tid) {
    int kc = kchunk * 32;
    int tap = kc >> 8;
    int i0 = kc & 255;
    uint32_t abase = smemU + stage * STAGE_BYTES;
    uint32_t bbase = abase + 8192;
#pragma unroll
    for (int q = 0; q < 2; q++) {
        int idx = tid + q * 256;
        int row = idx >> 2, c16 = idx & 3;
        int chunk = c16 ^ (row & 3) ^ ((row >> 2) & 1);
        cp16(abase + row * 64 + chunk * 16,
             g_xh + (size_t)(rbase + tap + row) * 256 + i0 + c16 * 8);
    }
#pragma unroll
    for (int q = 0; q < 2; q++) {
        int idx = tid + q * 256;
        int row = idx >> 2, c16 = idx & 3;
        int chunk = c16 ^ (row & 3) ^ ((row >> 2) & 1);
        cp16(bbase + row * 64 + chunk * 16,
             g_wh + (size_t)(n0 + row) * 768 + kc + c16 * 8);
    }
}

__global__ __launch_bounds__(256, 2)
void gemm_hmma(const float* __restrict__ bfv, const float* __restrict__ bbv) {
    extern __shared__ char smem[];
    uint32_t smemU = smem_u32(smem);
    const int tid = threadIdx.x;
    const int lane = tid & 31;
    const int w = tid >> 5;
    const int wm = w >> 1;          // 0..3  (32-row slices)
    const int wn = w & 1;           // 0..1  (64-col slices)
    const int n0 = blockIdx.x * 128;
    const int m0 = blockIdx.y * 128;
    const int batch = m0 >> 12;
    const int l0 = m0 & 4095;
    const int rbase = batch * LP + l0;

    // per-thread ldmatrix read offsets (within a stage)
    const int lr = lane & 7;
    const int grp = lane >> 3;
    const int arow = wm * 32 + (grp & 1) * 8 + lr;
    const int achk = (grp >> 1) ^ (arow & 3) ^ ((arow >> 2) & 1);
    const uint32_t aoff0 = (uint32_t)(arow * 64 + achk * 16);
    const int brow = wn * 64 + (grp >> 1) * 8 + lr;
    const int bchk = (grp & 1) ^ (brow & 3) ^ ((brow >> 2) & 1);
    const uint32_t boff0 = (uint32_t)(8192 + brow * 64 + bchk * 16);

    float acc[2][8][4];
#pragma unroll
    for (int mt = 0; mt < 2; mt++)
#pragma unroll
        for (int nt = 0; nt < 8; nt++)
#pragma unroll
            for (int r = 0; r < 4; r++) acc[mt][nt][r] = 0.f;

    // prologue: fill 3 stages
#pragma unroll
    for (int s = 0; s < STAGES - 1; s++) {
        gemm_issue(smemU, s, s, rbase, n0, tid);
        cp_commit();
    }

#pragma unroll 1
    for (int j = 0; j < NIT; j++) {
        cp_wait<STAGES - 2>();
        __syncthreads();
        if (j + STAGES - 1 < NIT)
            gemm_issue(smemU, (j + STAGES - 1) & (STAGES - 1), j + STAGES - 1, rbase, n0, tid);
        cp_commit();

        uint32_t stbase = smemU + (j & (STAGES - 1)) * STAGE_BYTES;
#pragma unroll
        for (int ks = 0; ks < 2; ks++) {
            uint32_t a[2][4], b[4][4];
#pragma unroll
            for (int mt = 0; mt < 2; mt++)
                ldsm4(a[mt], (stbase + aoff0 + mt * 1024) ^ (ks * 32));
#pragma unroll
            for (int np = 0; np < 4; np++)
                ldsm4(b[np], (stbase + boff0 + np * 1024) ^ (ks * 32));
#pragma unroll
            for (int mt = 0; mt < 2; mt++)
#pragma unroll
                for (int nt = 0; nt < 8; nt++)
                    mma_f16(acc[mt][nt], a[mt], b[nt >> 1][(nt & 1) * 2], b[nt >> 1][(nt & 1) * 2 + 1]);
        }
    }

    // epilogue: bias + activation -> fp16 gates
    const int ctype = (n0 >> 8) % 3;
    const float* bsrc = (n0 < 768) ? bfv : bbv;
    const int cofs = (n0 < 768) ? n0 : (n0 - 768);

#pragma unroll
    for (int mt = 0; mt < 2; mt++) {
        int mrow = m0 + wm * 32 + mt * 16 + (lane >> 2);
        __half* d0 = g_gates + (size_t)mrow * N_TOT + n0;
        __half* d1 = d0 + (size_t)8 * N_TOT;
#pragma unroll
        for (int nt = 0; nt < 8; nt++) {
            int cc = wn * 64 + nt * 8 + (lane & 3) * 2;
            float bb0 = bsrc[cofs + cc];
            float bb1 = bsrc[cofs + cc + 1];
            __half2 v0, v1;
            v0.x = __float2half_rn(actv(acc[mt][nt][0] + bb0, ctype));
            v0.y = __float2half_rn(actv(acc[mt][nt][1] + bb1, ctype));
            v1.x = __float2half_rn(actv(acc[mt][nt][2] + bb0, ctype));
            v1.y = __float2half_rn(actv(acc[mt][nt][3] + bb1, ctype));
            *(__half2*)(d0 + cc) = v0;
            *(__half2*)(d1 + cc) = v1;
        }
    }
}

// ---------------------------------------------------------------------------
// Chunked bidirectional fo-pool scan (fp16 gates, fp32 state)
// ---------------------------------------------------------------------------
__global__ void scanA() {
    int bid = blockIdx.x;
    int dir = bid >> 9;
    int rem = bid & 511;
    int b = rem >> 6;
    int ch = rem & 63;
    int d = threadIdx.x;

    float F = 1.f, c = 0.f;
    if (dir == 0) {
        const __half* gp = g_gates + (size_t)(b * LSEQ + ch * CHLEN) * N_TOT + d;
#pragma unroll 4
        for (int s = 0; s < CHLEN; s++) {
            float f = __half2float(gp[0]), z = __half2float(gp[512]);
            c = f * c + (1.f - f) * z;
            F *= f;
            gp += N_TOT;
        }
    } else {
        const __half* gp = g_gates + (size_t)(b * LSEQ + ch * CHLEN + CHLEN - 1) * N_TOT + 768 + d;
#pragma unroll 4
        for (int s = 0; s < CHLEN; s++) {
            float f = __half2float(gp[0]), z = __half2float(gp[512]);
            c = f * c + (1.f - f) * z;
            F *= f;
            gp -= N_TOT;
        }
    }
    int idx = ((dir * BATCH + b) * NCH + ch) * 256 + d;
    g_F[idx] = F;
    g_Cz[idx] = c;
}

__global__ void scanB() {
    int dir = blockIdx.x >> 3;
    int b = blockIdx.x & 7;
    int d = threadIdx.x;
    float c = 0.f;
    if (dir == 0) {
        for (int ch = 0; ch < NCH; ch++) {
            int idx = ((b) * NCH + ch) * 256 + d;
            g_init[idx] = c;
            c = g_F[idx] * c + g_Cz[idx];
        }
    } else {
        for (int ch = NCH - 1; ch >= 0; ch--) {
            int idx = ((BATCH + b) * NCH + ch) * 256 + d;
            g_init[idx] = c;
            c = g_F[idx] * c + g_Cz[idx];
        }
    }
}

__global__ void scanC(float* __restrict__ out) {
    int bid = blockIdx.x;
    int dir = bid >> 9;
    int rem = bid & 511;
    int b = rem >> 6;
    int ch = rem & 63;
    int d = threadIdx.x;
    const size_t OUT_HL = (size_t)BATCH * LSEQ * 512;

    float c = g_init[((dir * BATCH + b) * NCH + ch) * 256 + d];
    if (dir == 0) {
        const __half* gp = g_gates + (size_t)(b * LSEQ + ch * CHLEN) * N_TOT + d;
        float* op = out + (size_t)(b * LSEQ + ch * CHLEN) * 512 + d;
        float h = 0.f;
#pragma unroll 4
        for (int s = 0; s < CHLEN; s++) {
            float f = __half2float(gp[0]), o = __half2float(gp[256]), z = __half2float(gp[512]);
            c = f * c + (1.f - f) * z;
            h = c * o;
            *op = h;
            gp += N_TOT;
            op += 512;
        }
        if (ch == NCH - 1) {
            out[OUT_HL + b * 512 + d]        = h;
            out[OUT_HL + 4096 + b * 512 + d] = c;
        }
    } else {
        const __half* gp = g_gates + (size_t)(b * LSEQ + ch * CHLEN + CHLEN - 1) * N_TOT + 768 + d;
        float* op = out + (size_t)(b * LSEQ + ch * CHLEN + CHLEN - 1) * 512 + 256 + d;
        float h_first = 0.f, c_first = 0.f;
#pragma unroll 4
        for (int s = 0; s < CHLEN; s++) {
            float f = __half2float(gp[0]), o = __half2float(gp[256]), z = __half2float(gp[512]);
            c = f * c + (1.f - f) * z;
            float h = c * o;
            *op = h;
            if (s == 0) { h_first = h; c_first = c; }
            gp -= N_TOT;
            op -= 512;
        }
        if (ch == NCH - 1) {   // processed l = 4095 first
            out[OUT_HL + b * 512 + 256 + d]        = h_first;
            out[OUT_HL + 4096 + b * 512 + 256 + d] = c_first;
        }
    }
}

// ---------------------------------------------------------------------------
extern "C" void kernel_launch(void* const* d_in, const int* in_sizes, int n_in,
                              void* d_out, int out_size) {
    const float* x  = (const float*)d_in[0];
    const float* Wf = (const float*)d_in[2];
    const float* bf = (const float*)d_in[3];
    const float* Wb = (const float*)d_in[4];
    const float* bb = (const float*)d_in[5];
    float* out = (float*)d_out;

    cudaFuncSetAttribute(gemm_hmma, cudaFuncAttributeMaxDynamicSharedMemorySize, GEMM_SMEM);

    {
        int tot8 = BATCH * LP * DIN / 8;
        prep_x<<<(tot8 + 255) / 256, 256>>>(x);
    }
    {
        int tot = N_TOT * K_TOT;
        prep_w<<<(tot + 255) / 256, 256>>>(Wf, Wb);
    }
    gemm_hmma<<<dim3(12, 256), 256, GEMM_SMEM>>>(bf, bb);
    scanA<<<1024, 256>>>();
    scanB<<<16, 256>>>();
    scanC<<<1024, 256>>>(out);
}

// round 7
// speedup vs baseline: 7.2853x; 1.0220x over previous
#include <cuda_runtime.h>
#include <cuda_fp16.h>
#include <stdint.h>
#include <math.h>

#define BATCH 8
#define LSEQ  4096
#define DIN   256
#define M_TOT 32768
#define N_TOT 1536
#define K_TOT 768
#define LP    4098   // padded rows per batch (one zero row each side)

// ---------------- scratch (static device globals) ----------------
__device__ __align__(16) __half g_xh[BATCH * LP * DIN];
__device__ __align__(16) __half g_wh[N_TOT * K_TOT];
__device__ __align__(16) __half g_gates[(size_t)M_TOT * N_TOT];   // fp16 activated gates (~100MB)
// fused-scan scratch: 16 chains (dir,b) x 64 chunks x 256 channels
#define NCH 64
#define CHLEN 64
__device__ float g_aggF[16 * NCH * 256];
__device__ float g_aggC[16 * NCH * 256];
__device__ int   g_flag[16 * NCH];

// ---------------- PTX helpers (arch-agnostic, compute_80-era) ----------------
__device__ __forceinline__ uint32_t smem_u32(const void* p) {
    uint32_t a;
    asm("{ .reg .u64 t; cvta.to.shared.u64 t, %1; cvt.u32.u64 %0, t; }" : "=r"(a) : "l"(p));
    return a;
}
__device__ __forceinline__ void cp16(uint32_t dst, const void* src) {
    asm volatile("cp.async.cg.shared.global [%0], [%1], 16;" :: "r"(dst), "l"(src));
}
__device__ __forceinline__ void cp_commit() {
    asm volatile("cp.async.commit_group;" ::: "memory");
}
template<int N> __device__ __forceinline__ void cp_wait() {
    asm volatile("cp.async.wait_group %0;" :: "n"(N) : "memory");
}
__device__ __forceinline__ void ldsm4(uint32_t* r, uint32_t addr) {
    asm volatile("ldmatrix.sync.aligned.m8n8.x4.shared.b16 {%0,%1,%2,%3}, [%4];"
                 : "=r"(r[0]), "=r"(r[1]), "=r"(r[2]), "=r"(r[3]) : "r"(addr));
}
__device__ __forceinline__ void mma_f16(float* d, const uint32_t* a, uint32_t b0, uint32_t b1) {
    asm volatile("mma.sync.aligned.m16n8k16.row.col.f32.f16.f16.f32 "
                 "{%0,%1,%2,%3}, {%4,%5,%6,%7}, {%8,%9}, {%0,%1,%2,%3};"
                 : "+f"(d[0]), "+f"(d[1]), "+f"(d[2]), "+f"(d[3])
                 : "r"(a[0]), "r"(a[1]), "r"(a[2]), "r"(a[3]), "r"(b0), "r"(b1));
}

// ---------------------------------------------------------------------------
// Kernel 1: convert + pad x -> fp16  (rows: b*(L+2) + (l+1))
// ---------------------------------------------------------------------------
__global__ void prep_x(const float* __restrict__ x) {
    int idx = blockIdx.x * blockDim.x + threadIdx.x;
    const int TOT8 = BATCH * LP * DIN / 8;
    if (idx >= TOT8) return;
    int e0 = idx * 8;
    int b = e0 / (LP * DIN);
    int rem = e0 - b * LP * DIN;
    int r = rem / DIN;
    int i = rem - r * DIN;
    int l = r - 1;
    float v[8];
    if (l >= 0 && l < LSEQ) {
        const float4* src = (const float4*)(x + ((size_t)(b * LSEQ + l)) * DIN + i);
        float4 a = src[0], c = src[1];
        v[0]=a.x; v[1]=a.y; v[2]=a.z; v[3]=a.w; v[4]=c.x; v[5]=c.y; v[6]=c.z; v[7]=c.w;
    } else {
#pragma unroll
        for (int j = 0; j < 8; j++) v[j] = 0.f;
    }
    __half h[8];
#pragma unroll
    for (int j = 0; j < 8; j++) h[j] = __float2half_rn(v[j]);
    *(uint4*)(g_xh + e0) = *(uint4*)h;
}

// ---------------------------------------------------------------------------
// Kernel 2: weights -> [c][kk=tap*256+i] fp16 ; also resets scan flags
// ---------------------------------------------------------------------------
__global__ void prep_w(const float* __restrict__ Wf, const float* __restrict__ Wb) {
    int idx = blockIdx.x * blockDim.x + threadIdx.x;
    if (idx < 16 * NCH) g_flag[idx] = 0;
    if (idx >= N_TOT * K_TOT) return;
    int c = idx / K_TOT;
    int kk = idx - c * K_TOT;
    int tap = kk >> 8;
    int i = kk & 255;
    float v = (c < 768) ? Wf[c * 768 + i * 3 + tap] : Wb[(c - 768) * 768 + i * 3 + tap];
    g_wh[idx] = __float2half_rn(v);
}

// ---------------------------------------------------------------------------
// Kernel 3: fp16 HMMA GEMM + bias + activation -> g_gates (fp16)
// BM=128, BN=128, BK=32, 256 threads, warp tile 32x64, 4-stage cp.async
// 2 CTAs/SM for bubble overlap
// ---------------------------------------------------------------------------
#define STAGES 4
#define STAGE_BYTES 16384     // A: 128*64B = 8192, B: 128*64B = 8192
#define GEMM_SMEM (STAGES * STAGE_BYTES)
#define NIT 24

__device__ __forceinline__ float actv(float v, int ctype) {
    if (ctype == 2) {
        float t = __expf(-2.f * fabsf(v));
        float r = (1.f - t) / (1.f + t);
        return copysignf(r, v);
    }
    return 1.f / (1.f + __expf(-v));
}

__device__ __forceinline__ void gemm_issue(uint32_t smemU, int stage, int kchunk,
                                           int rbase, int n0, int tid) {
    int kc = kchunk * 32;
    int tap = kc >> 8;
    int i0 = kc & 255;
    uint32_t abase = smemU + stage * STAGE_BYTES;
    uint32_t bbase = abase + 8192;
#pragma unroll
    for (int q = 0; q < 2; q++) {
        int idx = tid + q * 256;
        int row = idx >> 2, c16 = idx & 3;
        int chunk = c16 ^ (row & 3) ^ ((row >> 2) & 1);
        cp16(abase + row * 64 + chunk * 16,
             g_xh + (size_t)(rbase + tap + row) * 256 + i0 + c16 * 8);
    }
#pragma unroll
    for (int q = 0; q < 2; q++) {
        int idx = tid + q * 256;
        int row = idx >> 2, c16 = idx & 3;
        int chunk = c16 ^ (row & 3) ^ ((row >> 2) & 1);
        cp16(bbase + row * 64 + chunk * 16,
             g_wh + (size_t)(n0 + row) * 768 + kc + c16 * 8);
    }
}

__global__ __launch_bounds__(256, 2)
void gemm_hmma(const float* __restrict__ bfv, const float* __restrict__ bbv) {
    extern __shared__ char smem[];
    uint32_t smemU = smem_u32(smem);
    const int tid = threadIdx.x;
    const int lane = tid & 31;
    const int w = tid >> 5;
    const int wm = w >> 1;          // 0..3  (32-row slices)
    const int wn = w & 1;           // 0..1  (64-col slices)
    const int n0 = blockIdx.x * 128;
    const int m0 = blockIdx.y * 128;
    const int batch = m0 >> 12;
    const int l0 = m0 & 4095;
    const int rbase = batch * LP + l0;

    // per-thread ldmatrix read offsets (within a stage)
    const int lr = lane & 7;
    const int grp = lane >> 3;
    const int arow = wm * 32 + (grp & 1) * 8 + lr;
    const int achk = (grp >> 1) ^ (arow & 3) ^ ((arow >> 2) & 1);
    const uint32_t aoff0 = (uint32_t)(arow * 64 + achk * 16);
    const int brow = wn * 64 + (grp >> 1) * 8 + lr;
    const int bchk = (grp & 1) ^ (brow & 3) ^ ((brow >> 2) & 1);
    const uint32_t boff0 = (uint32_t)(8192 + brow * 64 + bchk * 16);

    float acc[2][8][4];
#pragma unroll
    for (int mt = 0; mt < 2; mt++)
#pragma unroll
        for (int nt = 0; nt < 8; nt++)
#pragma unroll
            for (int r = 0; r < 4; r++) acc[mt][nt][r] = 0.f;

    // prologue: fill 3 stages
#pragma unroll
    for (int s = 0; s < STAGES - 1; s++) {
        gemm_issue(smemU, s, s, rbase, n0, tid);
        cp_commit();
    }

#pragma unroll 1
    for (int j = 0; j < NIT; j++) {
        cp_wait<STAGES - 2>();
        __syncthreads();
        if (j + STAGES - 1 < NIT)
            gemm_issue(smemU, (j + STAGES - 1) & (STAGES - 1), j + STAGES - 1, rbase, n0, tid);
        cp_commit();

        uint32_t stbase = smemU + (j & (STAGES - 1)) * STAGE_BYTES;
#pragma unroll
        for (int ks = 0; ks < 2; ks++) {
            uint32_t a[2][4], b[4][4];
#pragma unroll
            for (int mt = 0; mt < 2; mt++)
                ldsm4(a[mt], (stbase + aoff0 + mt * 1024) ^ (ks * 32));
#pragma unroll
            for (int np = 0; np < 4; np++)
                ldsm4(b[np], (stbase + boff0 + np * 1024) ^ (ks * 32));
#pragma unroll
            for (int mt = 0; mt < 2; mt++)
#pragma unroll
                for (int nt = 0; nt < 8; nt++)
                    mma_f16(acc[mt][nt], a[mt], b[nt >> 1][(nt & 1) * 2], b[nt >> 1][(nt & 1) * 2 + 1]);
        }
    }

    // epilogue: bias + activation -> fp16 gates
    const int ctype = (n0 >> 8) % 3;
    const float* bsrc = (n0 < 768) ? bfv : bbv;
    const int cofs = (n0 < 768) ? n0 : (n0 - 768);

#pragma unroll
    for (int mt = 0; mt < 2; mt++) {
        int mrow = m0 + wm * 32 + mt * 16 + (lane >> 2);
        __half* d0 = g_gates + (size_t)mrow * N_TOT + n0;
        __half* d1 = d0 + (size_t)8 * N_TOT;
#pragma unroll
        for (int nt = 0; nt < 8; nt++) {
            int cc = wn * 64 + nt * 8 + (lane & 3) * 2;
            float bb0 = bsrc[cofs + cc];
            float bb1 = bsrc[cofs + cc + 1];
            __half2 v0, v1;
            v0.x = __float2half_rn(actv(acc[mt][nt][0] + bb0, ctype));
            v0.y = __float2half_rn(actv(acc[mt][nt][1] + bb1, ctype));
            v1.x = __float2half_rn(actv(acc[mt][nt][2] + bb0, ctype));
            v1.y = __float2half_rn(actv(acc[mt][nt][3] + bb1, ctype));
            *(__half2*)(d0 + cc) = v0;
            *(__half2*)(d1 + cc) = v1;
        }
    }
}

// ---------------------------------------------------------------------------
// Kernel 4: fused single-pass bidirectional fo-pool scan
// bid -> (dir, b, pos); pos = position in scan order within the chain.
// Deterministic all-aggregate lookback: fold predecessors 0..pos-1 ascending
// (exactly matches a sequential chunk combine's rounding order).
// ---------------------------------------------------------------------------
__global__ void scan_fused(float* __restrict__ out) {
    const int bid = blockIdx.x;
    const int dir = bid >> 9;
    const int rem = bid & 511;
    const int b = rem >> 6;
    const int pos = rem & 63;
    const int ch = (dir == 0) ? pos : (NCH - 1 - pos);   // chunk index in l-space
    const int d = threadIdx.x;
    const int chain = dir * 8 + b;
    const int slot = chain * NCH + pos;
    const size_t OUT_HL = (size_t)BATCH * LSEQ * 512;

    // ---- pass 1: local aggregate (F = prod f, C = affine offset) ----
    float F = 1.f, C = 0.f;
    {
        const __half* gp;
        int step;
        if (dir == 0) {
            gp = g_gates + (size_t)(b * LSEQ + ch * CHLEN) * N_TOT + d;
            step = N_TOT;
        } else {
            gp = g_gates + (size_t)(b * LSEQ + ch * CHLEN + CHLEN - 1) * N_TOT + 768 + d;
            step = -N_TOT;
        }
#pragma unroll 4
        for (int s = 0; s < CHLEN; s++) {
            float f = __half2float(gp[0]), z = __half2float(gp[512]);
            C = f * C + (1.f - f) * z;
            F *= f;
            gp += step;
        }
    }
    g_aggF[slot * 256 + d] = F;
    g_aggC[slot * 256 + d] = C;
    __syncthreads();
    __threadfence();
    if (d == 0) atomicExch(&g_flag[slot], 1);

    // ---- lookback: wait for all predecessor aggregates, fold ascending ----
    float c = 0.f;
    if (pos > 0) {
        if (d < pos) {
            while (atomicAdd(&g_flag[chain * NCH + d], 0) == 0) {}
        }
        __syncthreads();
        __threadfence();
        const float* aF = g_aggF + (size_t)chain * NCH * 256 + d;
        const float* aC = g_aggC + (size_t)chain * NCH * 256 + d;
        for (int j = 0; j < pos; j++) {
            float Fj = aF[j * 256];
            float Cj = aC[j * 256];
            c = Fj * c + Cj;
        }
    }

    // ---- pass 2: re-scan chunk with correct init, write outputs ----
    if (dir == 0) {
        const __half* gp = g_gates + (size_t)(b * LSEQ + ch * CHLEN) * N_TOT + d;
        float* op = out + (size_t)(b * LSEQ + ch * CHLEN) * 512 + d;
        float h = 0.f;
#pragma unroll 4
        for (int s = 0; s < CHLEN; s++) {
            float f = __half2float(gp[0]), o = __half2float(gp[256]), z = __half2float(gp[512]);
            c = f * c + (1.f - f) * z;
            h = c * o;
            *op = h;
            gp += N_TOT;
            op += 512;
        }
        if (pos == NCH - 1) {
            out[OUT_HL + b * 512 + d]        = h;
            out[OUT_HL + 4096 + b * 512 + d] = c;
        }
    } else {
        const __half* gp = g_gates + (size_t)(b * LSEQ + ch * CHLEN + CHLEN - 1) * N_TOT + 768 + d;
        float* op = out + (size_t)(b * LSEQ + ch * CHLEN + CHLEN - 1) * 512 + 256 + d;
        float h_first = 0.f, c_first = 0.f;
#pragma unroll 4
        for (int s = 0; s < CHLEN; s++) {
            float f = __half2float(gp[0]), o = __half2float(gp[256]), z = __half2float(gp[512]);
            c = f * c + (1.f - f) * z;
            float h = c * o;
            *op = h;
            if (s == 0) { h_first = h; c_first = c; }
            gp -= N_TOT;
            op -= 512;
        }
        if (pos == 0) {    // pos 0 processes l = 4095 first -> rhidden[:, -1]
            out[OUT_HL + b * 512 + 256 + d]        = h_first;
            out[OUT_HL + 4096 + b * 512 + 256 + d] = c_first;
        }
    }
}

// ---------------------------------------------------------------------------
extern "C" void kernel_launch(void* const* d_in, const int* in_sizes, int n_in,
                              void* d_out, int out_size) {
    const float* x  = (const float*)d_in[0];
    const float* Wf = (const float*)d_in[2];
    const float* bf = (const float*)d_in[3];
    const float* Wb = (const float*)d_in[4];
    const float* bb = (const float*)d_in[5];
    float* out = (float*)d_out;

    cudaFuncSetAttribute(gemm_hmma, cudaFuncAttributeMaxDynamicSharedMemorySize, GEMM_SMEM);

    {
        int tot8 = BATCH * LP * DIN / 8;
        prep_x<<<(tot8 + 255) / 256, 256>>>(x);
    }
    {
        int tot = N_TOT * K_TOT;
        prep_w<<<(tot + 255) / 256, 256>>>(Wf, Wb);
    }
    gemm_hmma<<<dim3(12, 256), 256, GEMM_SMEM>>>(bf, bb);
    scan_fused<<<1024, 256>>>(out);
}

// round 8
// speedup vs baseline: 7.4330x; 1.0203x over previous
#include <cuda_runtime.h>
#include <cuda_fp16.h>
#include <stdint.h>
#include <math.h>

#define BATCH 8
#define LSEQ  4096
#define DIN   256
#define M_TOT 32768
#define N_TOT 1536
#define K_TOT 768
#define LP    4098   // padded rows per batch (one zero row each side)

// ---------------- scratch (static device globals) ----------------
__device__ __align__(16) __half g_xh[BATCH * LP * DIN];
__device__ __align__(16) __half g_wh[N_TOT * K_TOT];
__device__ __align__(16) __half g_gates[(size_t)M_TOT * N_TOT];   // fp16 activated gates (~100MB)
// fused-scan scratch: 16 chains (dir,b) x 64 chunks x 256 channels
#define NCH 64
#define CHLEN 64
__device__ float g_aggF[16 * NCH * 256];
__device__ float g_aggC[16 * NCH * 256];
__device__ int   g_flag[16 * NCH];

// ---------------- PTX helpers (arch-agnostic, compute_80-era) ----------------
__device__ __forceinline__ uint32_t smem_u32(const void* p) {
    uint32_t a;
    asm("{ .reg .u64 t; cvta.to.shared.u64 t, %1; cvt.u32.u64 %0, t; }" : "=r"(a) : "l"(p));
    return a;
}
__device__ __forceinline__ void cp16(uint32_t dst, const void* src) {
    asm volatile("cp.async.cg.shared.global [%0], [%1], 16;" :: "r"(dst), "l"(src));
}
__device__ __forceinline__ void cp_commit() {
    asm volatile("cp.async.commit_group;" ::: "memory");
}
template<int N> __device__ __forceinline__ void cp_wait() {
    asm volatile("cp.async.wait_group %0;" :: "n"(N) : "memory");
}
__device__ __forceinline__ void ldsm4(uint32_t* r, uint32_t addr) {
    asm volatile("ldmatrix.sync.aligned.m8n8.x4.shared.b16 {%0,%1,%2,%3}, [%4];"
                 : "=r"(r[0]), "=r"(r[1]), "=r"(r[2]), "=r"(r[3]) : "r"(addr));
}
__device__ __forceinline__ void mma_f16(float* d, const uint32_t* a, uint32_t b0, uint32_t b1) {
    asm volatile("mma.sync.aligned.m16n8k16.row.col.f32.f16.f16.f32 "
                 "{%0,%1,%2,%3}, {%4,%5,%6,%7}, {%8,%9}, {%0,%1,%2,%3};"
                 : "+f"(d[0]), "+f"(d[1]), "+f"(d[2]), "+f"(d[3])
                 : "r"(a[0]), "r"(a[1]), "r"(a[2]), "r"(a[3]), "r"(b0), "r"(b1));
}

// ---------------------------------------------------------------------------
// Kernel 1: merged prep — x pad/convert, weight relayout, scan-flag reset
// ---------------------------------------------------------------------------
__global__ void prep_all(const float* __restrict__ x,
                         const float* __restrict__ Wf,
                         const float* __restrict__ Wb) {
    int idx = blockIdx.x * blockDim.x + threadIdx.x;

    if (idx < 16 * NCH) g_flag[idx] = 0;

    // weight task: [c][kk=tap*256+i] fp16
    if (idx < N_TOT * K_TOT) {
        int c = idx / K_TOT;
        int kk = idx - c * K_TOT;
        int tap = kk >> 8;
        int i = kk & 255;
        float v = (c < 768) ? Wf[c * 768 + i * 3 + tap] : Wb[(c - 768) * 768 + i * 3 + tap];
        g_wh[idx] = __float2half_rn(v);
    }

    // x task: 8 elements per thread, rows b*(L+2) + (l+1)
    const int TOT8 = BATCH * LP * DIN / 8;
    if (idx < TOT8) {
        int e0 = idx * 8;
        int b = e0 / (LP * DIN);
        int rem = e0 - b * LP * DIN;
        int r = rem / DIN;
        int i = rem - r * DIN;
        int l = r - 1;
        float v[8];
        if (l >= 0 && l < LSEQ) {
            const float4* src = (const float4*)(x + ((size_t)(b * LSEQ + l)) * DIN + i);
            float4 a = src[0], c = src[1];
            v[0]=a.x; v[1]=a.y; v[2]=a.z; v[3]=a.w; v[4]=c.x; v[5]=c.y; v[6]=c.z; v[7]=c.w;
        } else {
#pragma unroll
            for (int j = 0; j < 8; j++) v[j] = 0.f;
        }
        __half h[8];
#pragma unroll
        for (int j = 0; j < 8; j++) h[j] = __float2half_rn(v[j]);
        *(uint4*)(g_xh + e0) = *(uint4*)h;
    }
}

// ---------------------------------------------------------------------------
// Kernel 2: persistent fp16 HMMA GEMM + bias + activation -> g_gates (fp16)
// BM=128, BN=128, BK=32, 256 threads, warp tile 32x64, 4-stage cp.async
// grid = 296 (one wave, 2 CTAs/SM), each CTA loops over tiles
// ---------------------------------------------------------------------------
#define STAGES 4
#define STAGE_BYTES 16384     // A: 128*64B = 8192, B: 128*64B = 8192
#define GEMM_SMEM (STAGES * STAGE_BYTES)
#define NIT 24
#define NTILES 3072           // 12 n-blocks x 256 m-blocks
#define GEMM_GRID 296

__device__ __forceinline__ float actv(float v, int ctype) {
    if (ctype == 2) {
        float t = __expf(-2.f * fabsf(v));
        float r = (1.f - t) / (1.f + t);
        return copysignf(r, v);
    }
    return 1.f / (1.f + __expf(-v));
}

__device__ __forceinline__ void gemm_issue(uint32_t smemU, int stage, int kchunk,
                                           int rbase, int n0, int tid) {
    int kc = kchunk * 32;
    int tap = kc >> 8;
    int i0 = kc & 255;
    uint32_t abase = smemU + stage * STAGE_BYTES;
    uint32_t bbase = abase + 8192;
#pragma unroll
    for (int q = 0; q < 2; q++) {
        int idx = tid + q * 256;
        int row = idx >> 2, c16 = idx & 3;
        int chunk = c16 ^ (row & 3) ^ ((row >> 2) & 1);
        cp16(abase + row * 64 + chunk * 16,
             g_xh + (size_t)(rbase + tap + row) * 256 + i0 + c16 * 8);
    }
#pragma unroll
    for (int q = 0; q < 2; q++) {
        int idx = tid + q * 256;
        int row = idx >> 2, c16 = idx & 3;
        int chunk = c16 ^ (row & 3) ^ ((row >> 2) & 1);
        cp16(bbase + row * 64 + chunk * 16,
             g_wh + (size_t)(n0 + row) * 768 + kc + c16 * 8);
    }
}

__global__ __launch_bounds__(256, 2)
void gemm_hmma(const float* __restrict__ bfv, const float* __restrict__ bbv) {
    extern __shared__ char smem[];
    uint32_t smemU = smem_u32(smem);
    const int tid = threadIdx.x;
    const int lane = tid & 31;
    const int w = tid >> 5;
    const int wm = w >> 1;          // 0..3  (32-row slices)
    const int wn = w & 1;           // 0..1  (64-col slices)

    // per-thread ldmatrix read offsets (tile-independent)
    const int lr = lane & 7;
    const int grp = lane >> 3;
    const int arow = wm * 32 + (grp & 1) * 8 + lr;
    const int achk = (grp >> 1) ^ (arow & 3) ^ ((arow >> 2) & 1);
    const uint32_t aoff0 = (uint32_t)(arow * 64 + achk * 16);
    const int brow = wn * 64 + (grp >> 1) * 8 + lr;
    const int bchk = (grp & 1) ^ (brow & 3) ^ ((brow >> 2) & 1);
    const uint32_t boff0 = (uint32_t)(8192 + brow * 64 + bchk * 16);

#pragma unroll 1
    for (int t = blockIdx.x; t < NTILES; t += GEMM_GRID) {
        const int n0 = (t % 12) * 128;
        const int m0 = (t / 12) * 128;
        const int batch = m0 >> 12;
        const int l0 = m0 & 4095;
        const int rbase = batch * LP + l0;

        __syncthreads();   // previous tile's compute fully done before smem reuse

        float acc[2][8][4];
#pragma unroll
        for (int mt = 0; mt < 2; mt++)
#pragma unroll
            for (int nt = 0; nt < 8; nt++)
#pragma unroll
                for (int r = 0; r < 4; r++) acc[mt][nt][r] = 0.f;

        // prologue: fill 3 stages
#pragma unroll
        for (int s = 0; s < STAGES - 1; s++) {
            gemm_issue(smemU, s, s, rbase, n0, tid);
            cp_commit();
        }

#pragma unroll 1
        for (int j = 0; j < NIT; j++) {
            cp_wait<STAGES - 2>();
            __syncthreads();
            if (j + STAGES - 1 < NIT)
                gemm_issue(smemU, (j + STAGES - 1) & (STAGES - 1), j + STAGES - 1, rbase, n0, tid);
            cp_commit();

            uint32_t stbase = smemU + (j & (STAGES - 1)) * STAGE_BYTES;
#pragma unroll
            for (int ks = 0; ks < 2; ks++) {
                uint32_t a[2][4], b[4][4];
#pragma unroll
                for (int mt = 0; mt < 2; mt++)
                    ldsm4(a[mt], (stbase + aoff0 + mt * 1024) ^ (ks * 32));
#pragma unroll
                for (int np = 0; np < 4; np++)
                    ldsm4(b[np], (stbase + boff0 + np * 1024) ^ (ks * 32));
#pragma unroll
                for (int mt = 0; mt < 2; mt++)
#pragma unroll
                    for (int nt = 0; nt < 8; nt++)
                        mma_f16(acc[mt][nt], a[mt], b[nt >> 1][(nt & 1) * 2], b[nt >> 1][(nt & 1) * 2 + 1]);
            }
        }

        // epilogue: bias + activation -> fp16 gates
        const int ctype = (n0 >> 8) % 3;
        const float* bsrc = (n0 < 768) ? bfv : bbv;
        const int cofs = (n0 < 768) ? n0 : (n0 - 768);

#pragma unroll
        for (int mt = 0; mt < 2; mt++) {
            int mrow = m0 + wm * 32 + mt * 16 + (lane >> 2);
            __half* d0 = g_gates + (size_t)mrow * N_TOT + n0;
            __half* d1 = d0 + (size_t)8 * N_TOT;
#pragma unroll
            for (int nt = 0; nt < 8; nt++) {
                int cc = wn * 64 + nt * 8 + (lane & 3) * 2;
                float bb0 = bsrc[cofs + cc];
                float bb1 = bsrc[cofs + cc + 1];
                __half2 v0, v1;
                v0.x = __float2half_rn(actv(acc[mt][nt][0] + bb0, ctype));
                v0.y = __float2half_rn(actv(acc[mt][nt][1] + bb1, ctype));
                v1.x = __float2half_rn(actv(acc[mt][nt][2] + bb0, ctype));
                v1.y = __float2half_rn(actv(acc[mt][nt][3] + bb1, ctype));
                *(__half2*)(d0 + cc) = v0;
                *(__half2*)(d1 + cc) = v1;
            }
        }
    }
}

// ---------------------------------------------------------------------------
// Kernel 3: fused single-pass bidirectional fo-pool scan
// Deterministic all-aggregate lookback (fold predecessors ascending)
// ---------------------------------------------------------------------------
__global__ void scan_fused(float* __restrict__ out) {
    const int bid = blockIdx.x;
    const int dir = bid >> 9;
    const int rem = bid & 511;
    const int b = rem >> 6;
    const int pos = rem & 63;
    const int ch = (dir == 0) ? pos : (NCH - 1 - pos);   // chunk index in l-space
    const int d = threadIdx.x;
    const int chain = dir * 8 + b;
    const int slot = chain * NCH + pos;
    const size_t OUT_HL = (size_t)BATCH * LSEQ * 512;

    // ---- pass 1: local aggregate (F = prod f, C = affine offset) ----
    float F = 1.f, C = 0.f;
    {
        const __half* gp;
        int step;
        if (dir == 0) {
            gp = g_gates + (size_t)(b * LSEQ + ch * CHLEN) * N_TOT + d;
            step = N_TOT;
        } else {
            gp = g_gates + (size_t)(b * LSEQ + ch * CHLEN + CHLEN - 1) * N_TOT + 768 + d;
            step = -N_TOT;
        }
#pragma unroll 4
        for (int s = 0; s < CHLEN; s++) {
            float f = __half2float(gp[0]), z = __half2float(gp[512]);
            C = f * C + (1.f - f) * z;
            F *= f;
            gp += step;
        }
    }
    g_aggF[slot * 256 + d] = F;
    g_aggC[slot * 256 + d] = C;
    __syncthreads();
    __threadfence();
    if (d == 0) atomicExch(&g_flag[slot], 1);

    // ---- lookback: wait for all predecessor aggregates, fold ascending ----
    float c = 0.f;
    if (pos > 0) {
        if (d < pos) {
            while (atomicAdd(&g_flag[chain * NCH + d], 0) == 0) {}
        }
        __syncthreads();
        __threadfence();
        const float* aF = g_aggF + (size_t)chain * NCH * 256 + d;
        const float* aC = g_aggC + (size_t)chain * NCH * 256 + d;
        for (int j = 0; j < pos; j++) {
            float Fj = aF[j * 256];
            float Cj = aC[j * 256];
            c = Fj * c + Cj;
        }
    }

    // ---- pass 2: re-scan chunk with correct init, write outputs ----
    if (dir == 0) {
        const __half* gp = g_gates + (size_t)(b * LSEQ + ch * CHLEN) * N_TOT + d;
        float* op = out + (size_t)(b * LSEQ + ch * CHLEN) * 512 + d;
        float h = 0.f;
#pragma unroll 4
        for (int s = 0; s < CHLEN; s++) {
            float f = __half2float(gp[0]), o = __half2float(gp[256]), z = __half2float(gp[512]);
            c = f * c + (1.f - f) * z;
            h = c * o;
            *op = h;
            gp += N_TOT;
            op += 512;
        }
        if (pos == NCH - 1) {
            out[OUT_HL + b * 512 + d]        = h;
            out[OUT_HL + 4096 + b * 512 + d] = c;
        }
    } else {
        const __half* gp = g_gates + (size_t)(b * LSEQ + ch * CHLEN + CHLEN - 1) * N_TOT + 768 + d;
        float* op = out + (size_t)(b * LSEQ + ch * CHLEN + CHLEN - 1) * 512 + 256 + d;
        float h_first = 0.f, c_first = 0.f;
#pragma unroll 4
        for (int s = 0; s < CHLEN; s++) {
            float f = __half2float(gp[0]), o = __half2float(gp[256]), z = __half2float(gp[512]);
            c = f * c + (1.f - f) * z;
            float h = c * o;
            *op = h;
            if (s == 0) { h_first = h; c_first = c; }
            gp -= N_TOT;
            op -= 512;
        }
        if (pos == 0) {    // pos 0 processes l = 4095 first -> rhidden[:, -1]
            out[OUT_HL + b * 512 + 256 + d]        = h_first;
            out[OUT_HL + 4096 + b * 512 + 256 + d] = c_first;
        }
    }
}

// ---------------------------------------------------------------------------
extern "C" void kernel_launch(void* const* d_in, const int* in_sizes, int n_in,
                              void* d_out, int out_size) {
    const float* x  = (const float*)d_in[0];
    const float* Wf = (const float*)d_in[2];
    const float* bf = (const float*)d_in[3];
    const float* Wb = (const float*)d_in[4];
    const float* bb = (const float*)d_in[5];
    float* out = (float*)d_out;

    cudaFuncSetAttribute(gemm_hmma, cudaFuncAttributeMaxDynamicSharedMemorySize, GEMM_SMEM);

    {
        int totw = N_TOT * K_TOT;                      // 1179648 (largest task)
        prep_all<<<(totw + 255) / 256, 256>>>(x, Wf, Wb);
    }
    gemm_hmma<<<GEMM_GRID, 256, GEMM_SMEM>>>(bf, bb);
    scan_fused<<<1024, 256>>>(out);
}